// round 4
// baseline (speedup 1.0000x reference)
#include <cuda_runtime.h>
#include <cuda_bf16.h>
#include <math.h>
#include <stdint.h>

// ---------------- problem constants ----------------
#define BATCH 16
#define NPTS 4096
#define NCTR 1024
#define NSAMP 32
#define INDIM 64
#define NROWS (BATCH*NCTR*NSAMP)          // 524288
#define NCTR_TOT (BATCH*NCTR)             // 16384
#define OUT_XYZ_ELEMS (NCTR_TOT*3)        // 49152
#define FPS_NB 16

// stats layout (32 slots per channel, sum then sq)
#define SUM0 0
#define SQ0  (64*32)
#define SUM1 (2*64*32)
#define SQ1  (3*64*32)
#define SUM2 (4*64*32)
#define SQ2  (4*64*32 + 128*32)
#define STATS_TOT (4*64*32 + 2*128*32)    // 16384

// affine layout
#define A0 0
#define C0A 64
#define A1 128
#define C1A 192
#define A2 256
#define C2A 384

// ---------------- scratch (static device memory; no allocs) ----------------
__device__ int   g_fps[NCTR_TOT];
__device__ int   g_bidx[NROWS];
__device__ float g_G[BATCH*NPTS*64];      // 16 MB
__device__ float g_C[NCTR_TOT*64];        // 4 MB
__device__ float g_Y1[NROWS*64];          // 134 MB
__device__ float g_mx[NCTR_TOT*128];      // 8 MB
__device__ float g_mn[NCTR_TOT*128];      // 8 MB
__device__ float g_stats[STATS_TOT];
__device__ float g_aff[512];

__device__ __forceinline__ unsigned long long u64min(unsigned long long a, unsigned long long b){
    return a < b ? a : b;
}

// =====================================================================
// MEGA kernel: blocks 0..15 = FPS (+ new_xyz gather + C) per batch;
//              blocks 16..  = G = feat@W0fT + xyz@W0xT + b0 (and stats zero)
// =====================================================================
__global__ void __launch_bounds__(256) mega_kernel(
        const float* __restrict__ xyz, const float* __restrict__ feat,
        const float* __restrict__ w0, const float* __restrict__ b0,
        float* __restrict__ out){
    extern __shared__ float sm[];
    int tid = threadIdx.x;

    if (blockIdx.x < FPS_NB){
        // ---------------- FPS branch ----------------
        float* sx = sm;               // 4096
        float* sy = sm + 4096;
        float* sz = sm + 8192;
        float (*srd)[8] = (float(*)[8])(sm + 12288);   // [2][8]
        int   (*sri)[8] = (int  (*)[8])(sm + 12288 + 16);

        int b = blockIdx.x;
        const float* xb = xyz + (size_t)b*NPTS*3;

        float px[16], py[16], pz[16], dist[16];
#pragma unroll
        for (int k = 0; k < 16; k++){
            int p = k*256 + tid;
            float x = xb[p*3], y = xb[p*3+1], z = xb[p*3+2];
            px[k]=x; py[k]=y; pz[k]=z; dist[k]=INFINITY;
            sx[p]=x; sy[p]=y; sz[p]=z;
        }
        if (tid == 0) g_fps[b*NCTR] = 0;
        float cx = xb[0], cy = xb[1], cz = xb[2];
        __syncthreads();

        int w = tid >> 5;
        for (int t = 1; t < NCTR; t++){
            float bd = -1.f; int bi = 0;
#pragma unroll
            for (int k = 0; k < 16; k++){
                float dx = px[k]-cx, dy = py[k]-cy, dz = pz[k]-cz;
                float d = fmaf(dx,dx, fmaf(dy,dy, dz*dz));
                float nd = fminf(dist[k], d);
                dist[k] = nd;
                if (nd > bd){ bd = nd; bi = k*256 + tid; }
            }
            // warp reduce: max dist, tie -> smaller global index
#pragma unroll
            for (int off = 16; off > 0; off >>= 1){
                float od = __shfl_down_sync(0xffffffffu, bd, off);
                int   oi = __shfl_down_sync(0xffffffffu, bi, off);
                if (od > bd || (od == bd && oi < bi)){ bd = od; bi = oi; }
            }
            int pb = t & 1;
            if ((tid & 31) == 0){ srd[pb][w] = bd; sri[pb][w] = bi; }
            __syncthreads();
            // every thread redundantly reduces the 8 warp partials
            float bd2 = srd[pb][0]; int bi2 = sri[pb][0];
#pragma unroll
            for (int ww = 1; ww < 8; ww++){
                float od = srd[pb][ww]; int oi = sri[pb][ww];
                if (od > bd2 || (od == bd2 && oi < bi2)){ bd2 = od; bi2 = oi; }
            }
            cx = sx[bi2]; cy = sy[bi2]; cz = sz[bi2];   // LDS broadcast
            if (tid == 0) g_fps[b*NCTR + t] = bi2;
        }
        __syncthreads();   // make g_fps writes visible to whole block

        // gather new_xyz from shared copy
        for (int i = tid; i < NCTR; i += 256){
            int idx = g_fps[b*NCTR + i];
            size_t o = (size_t)(b*NCTR + i)*3;
            out[o+0] = sx[idx]; out[o+1] = sy[idx]; out[o+2] = sz[idx];
        }
        __syncthreads();   // out visible within block

        // C = new_xyz @ W0xT for this batch
        for (int i = tid; i < NCTR*64; i += 256){
            int m = i >> 6, c = i & 63;
            const float* wr = w0 + c*67;
            size_t o = (size_t)(b*NCTR + m)*3;
            float acc = out[o+0]*wr[0];
            acc = fmaf(out[o+1], wr[1], acc);
            acc = fmaf(out[o+2], wr[2], acc);
            g_C[(size_t)(b*NCTR + m)*64 + c] = acc;
        }
    } else {
        // ---------------- G branch ----------------
        int gb = blockIdx.x - FPS_NB;
        if (gb < 16){
            for (int i = gb*1024 + tid; i < (gb+1)*1024; i += 256) g_stats[i] = 0.f;
        }
        float* w0s = sm;   // 64*67 floats
        for (int i = tid; i < 64*67; i += 256) w0s[i] = w0[i];
        __syncthreads();
        int p = gb*4 + (tid >> 6);
        int c = tid & 63;
        const float* fr = feat + (size_t)p*64;
        const float* wr = w0s + c*67;
        float acc = b0[c];
        acc = fmaf(xyz[p*3+0], wr[0], acc);
        acc = fmaf(xyz[p*3+1], wr[1], acc);
        acc = fmaf(xyz[p*3+2], wr[2], acc);
#pragma unroll 8
        for (int k = 0; k < 64; k++) acc = fmaf(fr[k], wr[3+k], acc);
        g_G[(size_t)p*64 + c] = acc;
    }
}

// ---------------- ball query + BN0 stats; 8 warps/block = 8 centers ----------------
__global__ void ballq_kernel(const float* __restrict__ xyz, const float* __restrict__ newxyz){
    __shared__ float sx[1024], sy[1024], sz[1024];
    __shared__ unsigned long long cbuf[8][256];
    __shared__ unsigned int usel[8][32];
    __shared__ float ssum[64], ssq[64];

    int tid = threadIdx.x, w = tid >> 5, l = tid & 31;
    int bx = blockIdx.x;
    int b = bx >> 7;                   // 128 blocks per batch
    int m = (bx & 127)*8 + w;          // center within batch
    int gm = b*NCTR + m;               // global center
    if (tid < 64){ ssum[tid] = 0.f; ssq[tid] = 0.f; }

    float qx = newxyz[gm*3], qy = newxyz[gm*3+1], qz = newxyz[gm*3+2];
    const float R2v = (float)(0.2*0.2);
    const float* xb = xyz + (size_t)b*NPTS*3;

    unsigned long long minkey = ~0ull;
    int cnt = 0;

    for (int ch = 0; ch < 4; ch++){
        __syncthreads();
        for (int i = tid; i < 1024; i += 256){
            int p = ch*1024 + i;
            sx[i] = xb[p*3]; sy[i] = xb[p*3+1]; sz[i] = xb[p*3+2];
        }
        __syncthreads();
        for (int j = 0; j < 32; j++){
            int pl = j*32 + l;
            float dx = qx - sx[pl], dy = qy - sy[pl], dz = qz - sz[pl];
            float d = fmaf(dx,dx, fmaf(dy,dy, dz*dz));
            int p = ch*1024 + pl;
            unsigned long long key = ((unsigned long long)__float_as_uint(d) << 32) | (unsigned)p;
            minkey = u64min(minkey, key);
            bool in = (d <= R2v);
            unsigned mask = __ballot_sync(0xffffffffu, in);
            if (in){
                int pos = cnt + __popc(mask & ((1u << l) - 1u));
                if (pos < 256) cbuf[w][pos] = key;
            }
            cnt += __popc(mask);
        }
    }
#pragma unroll
    for (int off = 16; off > 0; off >>= 1)
        minkey = u64min(minkey, __shfl_down_sync(0xffffffffu, minkey, off));
    minkey = __shfl_sync(0xffffffffu, minkey, 0);
    unsigned fill = (unsigned)minkey;

    if (cnt <= 32){
        unsigned v = (l < cnt) ? (unsigned)cbuf[w][l] : fill;
        usel[w][l] = v;
    } else {
        int n = cnt < 256 ? cnt : 256;
        unsigned long long e[8];
#pragma unroll
        for (int q = 0; q < 8; q++){ int p = q*32 + l; e[q] = (p < n) ? cbuf[w][p] : ~0ull; }
        for (int r = 0; r < 32; r++){
            unsigned long long loc = ~0ull;
#pragma unroll
            for (int q = 0; q < 8; q++) loc = u64min(loc, e[q]);
#pragma unroll
            for (int off = 16; off > 0; off >>= 1)
                loc = u64min(loc, __shfl_down_sync(0xffffffffu, loc, off));
            loc = __shfl_sync(0xffffffffu, loc, 0);
            if (l == r) usel[w][r] = (unsigned)loc;
#pragma unroll
            for (int q = 0; q < 8; q++) if (e[q] == loc) e[q] = ~0ull;
        }
    }
    __syncwarp();
    g_bidx[gm*32 + l] = (int)usel[w][l];

    // BN0 stats: y0 = G[idx] - C[m]
    float Cc1 = g_C[gm*64 + l], Cc2 = g_C[gm*64 + 32 + l];
    const float* Gb = g_G + (size_t)b*NPTS*64;
    float s1 = 0.f, q1 = 0.f, s2 = 0.f, q2 = 0.f;
    for (int s = 0; s < 32; s++){
        unsigned ip = usel[w][s];
        float ga = Gb[(size_t)ip*64 + l] - Cc1;
        float gb = Gb[(size_t)ip*64 + 32 + l] - Cc2;
        s1 += ga; q1 = fmaf(ga, ga, q1);
        s2 += gb; q2 = fmaf(gb, gb, q2);
    }
    atomicAdd(&ssum[l], s1);      atomicAdd(&ssq[l], q1);
    atomicAdd(&ssum[32+l], s2);   atomicAdd(&ssq[32+l], q2);
    __syncthreads();
    if (tid < 64){
        int slot = bx & 31;
        atomicAdd(&g_stats[SUM0 + tid*32 + slot], ssum[tid]);
        atomicAdd(&g_stats[SQ0  + tid*32 + slot], ssq[tid]);
    }
}

// ---------------- BN finalize ----------------
__global__ void fin_kernel(const float* __restrict__ gamma, const float* __restrict__ beta,
                           int sumoff, int sqoff, int aoff, int coff, int nch){
    int c = threadIdx.x;
    if (c >= nch) return;
    float s = 0.f, q = 0.f;
    for (int j = 0; j < 32; j++){ s += g_stats[sumoff + c*32 + j]; q += g_stats[sqoff + c*32 + j]; }
    const float invN = 1.f / (float)NROWS;
    float mean = s * invN;
    float var = q * invN - mean*mean;
    float rstd = rsqrtf(var + 1e-5f);
    float a = gamma[c] * rstd;
    g_aff[aoff + c] = a;
    g_aff[coff + c] = beta[c] - mean * a;
}

// ---------------- layer1: 128 rows x 64 cols, k-major smem, float4 LDS ----------------
#define X1P 132
#define W1P 68
__global__ void __launch_bounds__(128) l1_kernel(const float* __restrict__ w1, const float* __restrict__ b1){
    extern __shared__ float sm[];
    float* x1s = sm;                     // [64][X1P] k-major: x1s[k*X1P + r]
    float* w1s = sm + 64*X1P;            // [64][W1P] k-major: w1s[k*W1P + c]
    int*   sidx = (int*)(w1s + 64*W1P);  // 128
    float* ssum = (float*)(sidx + 128);  // 64
    float* ssq  = ssum + 64;             // 64

    int tid = threadIdx.x;
    int m0 = blockIdx.x * 4;
    int b = m0 >> 10;

    if (tid < 64){ ssum[tid] = 0.f; ssq[tid] = 0.f; }
    sidx[tid] = g_bidx[m0*32 + tid];
    // transpose weights into k-major (coalesced read, 4-way-conflict write once)
    for (int i = tid; i < 64*64; i += 128){
        int c = i >> 6, k = i & 63;
        w1s[k*W1P + c] = w1[i];
    }
    __syncthreads();

    const float* Gb = g_G + (size_t)b*NPTS*64;
#pragma unroll 8
    for (int e = 0; e < 64; e++){
        int flat = e*128 + tid;
        int r = flat >> 6, c = flat & 63;
        int gm = m0 + (r >> 5);
        float y = Gb[(size_t)sidx[r]*64 + c] - g_C[gm*64 + c];
        x1s[c*X1P + r] = fmaxf(fmaf(g_aff[A0 + c], y, g_aff[C0A + c]), 0.f);
    }
    __syncthreads();

    int rg = tid >> 3, cg = tid & 7;
    int rb = rg*8, cb = cg*8;
    float acc[8][8];
#pragma unroll
    for (int i = 0; i < 8; i++)
#pragma unroll
        for (int j = 0; j < 8; j++) acc[i][j] = 0.f;

#pragma unroll 4
    for (int k = 0; k < 64; k++){
        float4 x0 = *(const float4*)&x1s[k*X1P + rb];
        float4 x1 = *(const float4*)&x1s[k*X1P + rb + 4];
        float4 w0v = *(const float4*)&w1s[k*W1P + cb];
        float4 w1v = *(const float4*)&w1s[k*W1P + cb + 4];
        float xv[8] = {x0.x,x0.y,x0.z,x0.w,x1.x,x1.y,x1.z,x1.w};
        float wv[8] = {w0v.x,w0v.y,w0v.z,w0v.w,w1v.x,w1v.y,w1v.z,w1v.w};
#pragma unroll
        for (int i = 0; i < 8; i++)
#pragma unroll
            for (int j = 0; j < 8; j++) acc[i][j] = fmaf(xv[i], wv[j], acc[i][j]);
    }

    float tsum[8], tsq[8];
#pragma unroll
    for (int j = 0; j < 8; j++){ tsum[j] = 0.f; tsq[j] = 0.f; }
#pragma unroll
    for (int i = 0; i < 8; i++){
        size_t R = (size_t)m0*32 + rb + i;
#pragma unroll
        for (int j = 0; j < 8; j++){
            float y = acc[i][j] + b1[cb+j];
            g_Y1[R*64 + cb + j] = y;
            tsum[j] += y; tsq[j] = fmaf(y, y, tsq[j]);
        }
    }
#pragma unroll
    for (int j = 0; j < 8; j++){
        atomicAdd(&ssum[cb+j], tsum[j]);
        atomicAdd(&ssq[cb+j], tsq[j]);
    }
    __syncthreads();
    if (tid < 64){
        int slot = blockIdx.x & 31;
        atomicAdd(&g_stats[SUM1 + tid*32 + slot], ssum[tid]);
        atomicAdd(&g_stats[SQ1  + tid*32 + slot], ssq[tid]);
    }
}

// ---------------- layer2: 64 rows x 128 cols, k-major smem, float4 LDS, fused pool ----------------
#define X2P 68
#define W2P 132
__global__ void __launch_bounds__(128) l2_kernel(const float* __restrict__ w2, const float* __restrict__ b2){
    extern __shared__ float sm[];
    float* x2s  = sm;                    // [64][X2P]: x2s[k*X2P + r]
    float* w2s  = sm + 64*X2P;           // [64][W2P]: w2s[k*W2P + c]
    float* pmax = w2s + 64*W2P;          // 8*128
    float* pmin = pmax + 8*128;          // 8*128
    float* ssum = pmin + 8*128;          // 128
    float* ssq  = ssum + 128;            // 128

    int tid = threadIdx.x;
    int m0 = blockIdx.x * 2;

    ssum[tid] = 0.f; ssq[tid] = 0.f;
    for (int i = tid; i < 128*64; i += 128){
        int c = i >> 6, k = i & 63;
        w2s[k*W2P + c] = w2[i];
    }
    for (int i = tid; i < 64*64; i += 128){
        int r = i >> 6, c = i & 63;
        float y = g_Y1[((size_t)m0*32 + r)*64 + c];
        x2s[c*X2P + r] = fmaxf(fmaf(g_aff[A1 + c], y, g_aff[C1A + c]), 0.f);
    }
    __syncthreads();

    int rg = tid >> 4, cg = tid & 15;
    int rb = rg*8, cb = cg*8;
    float acc[8][8];
#pragma unroll
    for (int i = 0; i < 8; i++)
#pragma unroll
        for (int j = 0; j < 8; j++) acc[i][j] = 0.f;

#pragma unroll 4
    for (int k = 0; k < 64; k++){
        float4 x0 = *(const float4*)&x2s[k*X2P + rb];
        float4 x1 = *(const float4*)&x2s[k*X2P + rb + 4];
        float4 w0v = *(const float4*)&w2s[k*W2P + cb];
        float4 w1v = *(const float4*)&w2s[k*W2P + cb + 4];
        float xv[8] = {x0.x,x0.y,x0.z,x0.w,x1.x,x1.y,x1.z,x1.w};
        float wv[8] = {w0v.x,w0v.y,w0v.z,w0v.w,w1v.x,w1v.y,w1v.z,w1v.w};
#pragma unroll
        for (int i = 0; i < 8; i++)
#pragma unroll
            for (int j = 0; j < 8; j++) acc[i][j] = fmaf(xv[i], wv[j], acc[i][j]);
    }

    float tmax[8], tmin[8], tsum[8], tsq[8];
#pragma unroll
    for (int j = 0; j < 8; j++){ tmax[j] = -INFINITY; tmin[j] = INFINITY; tsum[j] = 0.f; tsq[j] = 0.f; }
#pragma unroll
    for (int i = 0; i < 8; i++)
#pragma unroll
        for (int j = 0; j < 8; j++){
            float y = acc[i][j] + b2[cb+j];
            tmax[j] = fmaxf(tmax[j], y);
            tmin[j] = fminf(tmin[j], y);
            tsum[j] += y; tsq[j] = fmaf(y, y, tsq[j]);
        }
#pragma unroll
    for (int j = 0; j < 8; j++){
        pmax[rg*128 + cb + j] = tmax[j];
        pmin[rg*128 + cb + j] = tmin[j];
        atomicAdd(&ssum[cb+j], tsum[j]);
        atomicAdd(&ssq[cb+j], tsq[j]);
    }
    __syncthreads();

    for (int i2 = tid; i2 < 256; i2 += 128){
        int cent = i2 >> 7, c = i2 & 127;
        float mx = -INFINITY, mn = INFINITY;
#pragma unroll
        for (int r4 = 0; r4 < 4; r4++){
            mx = fmaxf(mx, pmax[(cent*4 + r4)*128 + c]);
            mn = fminf(mn, pmin[(cent*4 + r4)*128 + c]);
        }
        g_mx[(size_t)(m0+cent)*128 + c] = mx;
        g_mn[(size_t)(m0+cent)*128 + c] = mn;
    }
    int slot = blockIdx.x & 31;
    atomicAdd(&g_stats[SUM2 + tid*32 + slot], ssum[tid]);
    atomicAdd(&g_stats[SQ2  + tid*32 + slot], ssq[tid]);
}

// ---------------- final: BN2+ReLU on pooled extremum ----------------
__global__ void out_kernel(float* __restrict__ out){
    int i = blockIdx.x*256 + threadIdx.x;   // NCTR_TOT*128
    int c = i & 127;
    float a = g_aff[A2 + c];
    float v = (a >= 0.f) ? g_mx[i] : g_mn[i];
    out[OUT_XYZ_ELEMS + i] = fmaxf(fmaf(a, v, g_aff[C2A + c]), 0.f);
}

// ---------------- host launcher ----------------
extern "C" void kernel_launch(void* const* d_in, const int* in_sizes, int n_in,
                              void* d_out, int out_size){
    const float* xyz   = (const float*)d_in[0];
    const float* feat  = (const float*)d_in[1];
    const float* w0 = (const float*)d_in[2];
    const float* b0 = (const float*)d_in[3];
    const float* g0 = (const float*)d_in[4];
    const float* be0 = (const float*)d_in[5];
    const float* w1 = (const float*)d_in[6];
    const float* b1 = (const float*)d_in[7];
    const float* g1 = (const float*)d_in[8];
    const float* be1 = (const float*)d_in[9];
    const float* w2 = (const float*)d_in[10];
    const float* b2 = (const float*)d_in[11];
    const float* g2 = (const float*)d_in[12];
    const float* be2 = (const float*)d_in[13];
    float* out = (float*)d_out;

    static const int MEGA_SMEM = (12288 + 64) * 4;                       // ~49.4 KB
    static const int L1_SMEM  = (64*X1P + 64*W1P + 128 + 128) * 4;       // ~52 KB
    static const int L2_SMEM  = (64*X2P + 64*W2P + 2*8*128 + 256) * 4;   // ~61 KB
    cudaFuncSetAttribute(mega_kernel, cudaFuncAttributeMaxDynamicSharedMemorySize, MEGA_SMEM);
    cudaFuncSetAttribute(l1_kernel,  cudaFuncAttributeMaxDynamicSharedMemorySize, L1_SMEM);
    cudaFuncSetAttribute(l2_kernel,  cudaFuncAttributeMaxDynamicSharedMemorySize, L2_SMEM);

    mega_kernel<<<FPS_NB + BATCH*NPTS/4, 256, MEGA_SMEM>>>(xyz, feat, w0, b0, out);
    ballq_kernel<<<NCTR_TOT/8, 256>>>(xyz, out);
    fin_kernel<<<1, 128>>>(g0, be0, SUM0, SQ0, A0, C0A, 64);
    l1_kernel<<<NCTR_TOT/4, 128, L1_SMEM>>>(w1, b1);
    fin_kernel<<<1, 128>>>(g1, be1, SUM1, SQ1, A1, C1A, 64);
    l2_kernel<<<NCTR_TOT/2, 128, L2_SMEM>>>(w2, b2);
    fin_kernel<<<1, 128>>>(g2, be2, SUM2, SQ2, A2, C2A, 128);
    out_kernel<<<NCTR_TOT*128/256, 256>>>(out);
}

// round 5
// speedup vs baseline: 1.9374x; 1.9374x over previous
#include <cuda_runtime.h>
#include <cuda_bf16.h>
#include <math.h>
#include <stdint.h>

// ---------------- problem constants ----------------
#define BATCH 16
#define NPTS 4096
#define NCTR 1024
#define NSAMP 32
#define INDIM 64
#define NROWS (BATCH*NCTR*NSAMP)          // 524288
#define NCTR_TOT (BATCH*NCTR)             // 16384
#define OUT_XYZ_ELEMS (NCTR_TOT*3)        // 49152
#define FPS_NB 16

// stats layout (32 slots per channel, sum then sq)
#define SUM0 0
#define SQ0  (64*32)
#define SUM1 (2*64*32)
#define SQ1  (3*64*32)
#define SUM2 (4*64*32)
#define SQ2  (4*64*32 + 128*32)
#define STATS_TOT (4*64*32 + 2*128*32)    // 16384

// affine layout
#define A0 0
#define C0A 64
#define A1 128
#define C1A 192
#define A2 256
#define C2A 384

// ---------------- scratch (static device memory; no allocs) ----------------
__device__ int   g_fps[NCTR_TOT];
__device__ int   g_bidx[NROWS];
__device__ float g_G[BATCH*NPTS*64];      // 16 MB
__device__ float g_C[NCTR_TOT*64];        // 4 MB
__device__ float g_Y1[NROWS*64];          // 134 MB
__device__ float g_mx[NCTR_TOT*128];      // 8 MB
__device__ float g_mn[NCTR_TOT*128];      // 8 MB
__device__ float g_stats[STATS_TOT];
__device__ float g_aff[512];

__device__ __forceinline__ unsigned long long u64min(unsigned long long a, unsigned long long b){
    return a < b ? a : b;
}
__device__ __forceinline__ uint32_t f2tf32(float x){
    uint32_t r; asm("cvt.rna.tf32.f32 %0, %1;" : "=r"(r) : "f"(x)); return r;
}
__device__ __forceinline__ void mma_tf32(float4& d, const uint32_t* a, const uint32_t* b){
    asm volatile("mma.sync.aligned.m16n8k8.row.col.f32.tf32.tf32.f32 "
                 "{%0,%1,%2,%3},{%4,%5,%6,%7},{%8,%9},{%0,%1,%2,%3};"
                 : "+f"(d.x),"+f"(d.y),"+f"(d.z),"+f"(d.w)
                 : "r"(a[0]),"r"(a[1]),"r"(a[2]),"r"(a[3]),"r"(b[0]),"r"(b[1]));
}

// =====================================================================
// MEGA kernel: blocks 0..15 = FPS (+ new_xyz gather + C) per batch;
//              blocks 16..  = G = feat@W0fT + xyz@W0xT + b0 (and stats zero)
// =====================================================================
__global__ void __launch_bounds__(256) mega_kernel(
        const float* __restrict__ xyz, const float* __restrict__ feat,
        const float* __restrict__ w0, const float* __restrict__ b0,
        float* __restrict__ out){
    extern __shared__ float sm[];
    int tid = threadIdx.x;

    if (blockIdx.x < FPS_NB){
        float* sx = sm;               // 4096
        float* sy = sm + 4096;
        float* sz = sm + 8192;
        float (*srd)[8] = (float(*)[8])(sm + 12288);   // [2][8]
        int   (*sri)[8] = (int  (*)[8])(sm + 12288 + 16);

        int b = blockIdx.x;
        const float* xb = xyz + (size_t)b*NPTS*3;

        float px[16], py[16], pz[16], dist[16];
#pragma unroll
        for (int k = 0; k < 16; k++){
            int p = k*256 + tid;
            float x = xb[p*3], y = xb[p*3+1], z = xb[p*3+2];
            px[k]=x; py[k]=y; pz[k]=z; dist[k]=INFINITY;
            sx[p]=x; sy[p]=y; sz[p]=z;
        }
        if (tid == 0) g_fps[b*NCTR] = 0;
        float cx = xb[0], cy = xb[1], cz = xb[2];
        __syncthreads();

        int w = tid >> 5;
        for (int t = 1; t < NCTR; t++){
            float bd = -1.f; int bi = 0;
#pragma unroll
            for (int k = 0; k < 16; k++){
                float dx = px[k]-cx, dy = py[k]-cy, dz = pz[k]-cz;
                float d = fmaf(dx,dx, fmaf(dy,dy, dz*dz));
                float nd = fminf(dist[k], d);
                dist[k] = nd;
                if (nd > bd){ bd = nd; bi = k*256 + tid; }
            }
#pragma unroll
            for (int off = 16; off > 0; off >>= 1){
                float od = __shfl_down_sync(0xffffffffu, bd, off);
                int   oi = __shfl_down_sync(0xffffffffu, bi, off);
                if (od > bd || (od == bd && oi < bi)){ bd = od; bi = oi; }
            }
            int pb = t & 1;
            if ((tid & 31) == 0){ srd[pb][w] = bd; sri[pb][w] = bi; }
            __syncthreads();
            float bd2 = srd[pb][0]; int bi2 = sri[pb][0];
#pragma unroll
            for (int ww = 1; ww < 8; ww++){
                float od = srd[pb][ww]; int oi = sri[pb][ww];
                if (od > bd2 || (od == bd2 && oi < bi2)){ bd2 = od; bi2 = oi; }
            }
            cx = sx[bi2]; cy = sy[bi2]; cz = sz[bi2];
            if (tid == 0) g_fps[b*NCTR + t] = bi2;
        }
        __syncthreads();

        for (int i = tid; i < NCTR; i += 256){
            int idx = g_fps[b*NCTR + i];
            size_t o = (size_t)(b*NCTR + i)*3;
            out[o+0] = sx[idx]; out[o+1] = sy[idx]; out[o+2] = sz[idx];
        }
        __syncthreads();

        for (int i = tid; i < NCTR*64; i += 256){
            int m = i >> 6, c = i & 63;
            const float* wr = w0 + c*67;
            size_t o = (size_t)(b*NCTR + m)*3;
            float acc = out[o+0]*wr[0];
            acc = fmaf(out[o+1], wr[1], acc);
            acc = fmaf(out[o+2], wr[2], acc);
            g_C[(size_t)(b*NCTR + m)*64 + c] = acc;
        }
    } else {
        int gb = blockIdx.x - FPS_NB;
        if (gb < 16){
            for (int i = gb*1024 + tid; i < (gb+1)*1024; i += 256) g_stats[i] = 0.f;
        }
        float* w0s = sm;   // 64*67 floats
        for (int i = tid; i < 64*67; i += 256) w0s[i] = w0[i];
        __syncthreads();
        int p = gb*4 + (tid >> 6);
        int c = tid & 63;
        const float* fr = feat + (size_t)p*64;
        const float* wr = w0s + c*67;
        float acc = b0[c];
        acc = fmaf(xyz[p*3+0], wr[0], acc);
        acc = fmaf(xyz[p*3+1], wr[1], acc);
        acc = fmaf(xyz[p*3+2], wr[2], acc);
#pragma unroll 8
        for (int k = 0; k < 64; k++) acc = fmaf(fr[k], wr[3+k], acc);
        g_G[(size_t)p*64 + c] = acc;
    }
}

// ---------------- ball query + BN0 stats; 8 warps/block = 8 centers ----------------
__global__ void ballq_kernel(const float* __restrict__ xyz, const float* __restrict__ newxyz){
    __shared__ float sx[1024], sy[1024], sz[1024];
    __shared__ unsigned long long cbuf[8][256];
    __shared__ unsigned int usel[8][32];
    __shared__ float ssum[64], ssq[64];

    int tid = threadIdx.x, w = tid >> 5, l = tid & 31;
    int bx = blockIdx.x;
    int b = bx >> 7;
    int m = (bx & 127)*8 + w;
    int gm = b*NCTR + m;
    if (tid < 64){ ssum[tid] = 0.f; ssq[tid] = 0.f; }

    float qx = newxyz[gm*3], qy = newxyz[gm*3+1], qz = newxyz[gm*3+2];
    const float R2v = (float)(0.2*0.2);
    const float* xb = xyz + (size_t)b*NPTS*3;

    unsigned long long minkey = ~0ull;
    int cnt = 0;

    for (int ch = 0; ch < 4; ch++){
        __syncthreads();
        for (int i = tid; i < 1024; i += 256){
            int p = ch*1024 + i;
            sx[i] = xb[p*3]; sy[i] = xb[p*3+1]; sz[i] = xb[p*3+2];
        }
        __syncthreads();
        for (int j = 0; j < 32; j++){
            int pl = j*32 + l;
            float dx = qx - sx[pl], dy = qy - sy[pl], dz = qz - sz[pl];
            float d = fmaf(dx,dx, fmaf(dy,dy, dz*dz));
            int p = ch*1024 + pl;
            unsigned long long key = ((unsigned long long)__float_as_uint(d) << 32) | (unsigned)p;
            minkey = u64min(minkey, key);
            bool in = (d <= R2v);
            unsigned mask = __ballot_sync(0xffffffffu, in);
            if (in){
                int pos = cnt + __popc(mask & ((1u << l) - 1u));
                if (pos < 256) cbuf[w][pos] = key;
            }
            cnt += __popc(mask);
        }
    }
#pragma unroll
    for (int off = 16; off > 0; off >>= 1)
        minkey = u64min(minkey, __shfl_down_sync(0xffffffffu, minkey, off));
    minkey = __shfl_sync(0xffffffffu, minkey, 0);
    unsigned fill = (unsigned)minkey;

    if (cnt <= 32){
        unsigned v = (l < cnt) ? (unsigned)cbuf[w][l] : fill;
        usel[w][l] = v;
    } else {
        int n = cnt < 256 ? cnt : 256;
        unsigned long long e[8];
#pragma unroll
        for (int q = 0; q < 8; q++){ int p = q*32 + l; e[q] = (p < n) ? cbuf[w][p] : ~0ull; }
        for (int r = 0; r < 32; r++){
            unsigned long long loc = ~0ull;
#pragma unroll
            for (int q = 0; q < 8; q++) loc = u64min(loc, e[q]);
#pragma unroll
            for (int off = 16; off > 0; off >>= 1)
                loc = u64min(loc, __shfl_down_sync(0xffffffffu, loc, off));
            loc = __shfl_sync(0xffffffffu, loc, 0);
            if (l == r) usel[w][r] = (unsigned)loc;
#pragma unroll
            for (int q = 0; q < 8; q++) if (e[q] == loc) e[q] = ~0ull;
        }
    }
    __syncwarp();
    g_bidx[gm*32 + l] = (int)usel[w][l];

    float Cc1 = g_C[gm*64 + l], Cc2 = g_C[gm*64 + 32 + l];
    const float* Gb = g_G + (size_t)b*NPTS*64;
    float s1 = 0.f, q1 = 0.f, s2 = 0.f, q2 = 0.f;
    for (int s = 0; s < 32; s++){
        unsigned ip = usel[w][s];
        float ga = Gb[(size_t)ip*64 + l] - Cc1;
        float gb = Gb[(size_t)ip*64 + 32 + l] - Cc2;
        s1 += ga; q1 = fmaf(ga, ga, q1);
        s2 += gb; q2 = fmaf(gb, gb, q2);
    }
    atomicAdd(&ssum[l], s1);      atomicAdd(&ssq[l], q1);
    atomicAdd(&ssum[32+l], s2);   atomicAdd(&ssq[32+l], q2);
    __syncthreads();
    if (tid < 64){
        int slot = bx & 31;
        atomicAdd(&g_stats[SUM0 + tid*32 + slot], ssum[tid]);
        atomicAdd(&g_stats[SQ0  + tid*32 + slot], ssq[tid]);
    }
}

// ---------------- BN finalize ----------------
__global__ void fin_kernel(const float* __restrict__ gamma, const float* __restrict__ beta,
                           int sumoff, int sqoff, int aoff, int coff, int nch){
    int c = threadIdx.x;
    if (c >= nch) return;
    float s = 0.f, q = 0.f;
    for (int j = 0; j < 32; j++){ s += g_stats[sumoff + c*32 + j]; q += g_stats[sqoff + c*32 + j]; }
    const float invN = 1.f / (float)NROWS;
    float mean = s * invN;
    float var = q * invN - mean*mean;
    float rstd = rsqrtf(var + 1e-5f);
    float a = gamma[c] * rstd;
    g_aff[aoff + c] = a;
    g_aff[coff + c] = beta[c] - mean * a;
}

// ---------------- layer1: tf32 MMA, 128 rows x 64 cols ----------------
#define P1 68
__global__ void __launch_bounds__(128) l1_kernel(const float* __restrict__ w1, const float* __restrict__ b1){
    extern __shared__ float smf[];
    uint32_t* xs = (uint32_t*)smf;        // [128][P1] row-major (r, k), tf32 bits
    uint32_t* ws = xs + 128*P1;           // [64][P1]  (n, k), tf32 bits
    int*   sidx = (int*)(ws + 64*P1);     // 128
    float* ssum = (float*)(sidx + 128);   // 64
    float* ssq  = ssum + 64;              // 64

    int tid = threadIdx.x;
    int w = tid >> 5, lane = tid & 31;
    int g = lane >> 2, tig = lane & 3;
    int m0 = blockIdx.x * 4;
    int b = m0 >> 10;

    if (tid < 64){ ssum[tid] = 0.f; ssq[tid] = 0.f; }
    sidx[tid] = g_bidx[m0*32 + tid];
    for (int i = tid; i < 64*64; i += 128){
        int c = i >> 6, k = i & 63;
        ws[c*P1 + k] = f2tf32(w1[i]);
    }
    __syncthreads();

    const float* Gb = g_G + (size_t)b*NPTS*64;
#pragma unroll 8
    for (int e = 0; e < 64; e++){
        int flat = e*128 + tid;
        int r = flat >> 6, c = flat & 63;
        int gm = m0 + (r >> 5);
        float y = Gb[(size_t)sidx[r]*64 + c] - g_C[gm*64 + c];
        xs[r*P1 + c] = f2tf32(fmaxf(fmaf(g_aff[A0 + c], y, g_aff[C0A + c]), 0.f));
    }
    __syncthreads();

    // warp w: rows [w*32, w*32+32) (2 m-tiles), cols 0..63 (8 n-tiles)
    float4 d[2][8];
#pragma unroll
    for (int mt = 0; mt < 2; mt++)
#pragma unroll
        for (int nt = 0; nt < 8; nt++) d[mt][nt] = make_float4(0.f,0.f,0.f,0.f);

    int xbase = (w*32 + g)*P1;
    int wbase = g*P1;
#pragma unroll
    for (int kt = 0; kt < 8; kt++){
        int k0 = kt*8 + tig;
        uint32_t a[2][4];
#pragma unroll
        for (int mt = 0; mt < 2; mt++){
            int ro = xbase + mt*16*P1;
            a[mt][0] = xs[ro + k0];
            a[mt][1] = xs[ro + 8*P1 + k0];
            a[mt][2] = xs[ro + k0 + 4];
            a[mt][3] = xs[ro + 8*P1 + k0 + 4];
        }
        uint32_t bf[8][2];
#pragma unroll
        for (int nt = 0; nt < 8; nt++){
            int no = wbase + nt*8*P1;
            bf[nt][0] = ws[no + k0];
            bf[nt][1] = ws[no + k0 + 4];
        }
#pragma unroll
        for (int nt = 0; nt < 8; nt++)
#pragma unroll
            for (int mt = 0; mt < 2; mt++)
                mma_tf32(d[mt][nt], a[mt], bf[nt]);
    }

    // epilogue: bias, store Y1, stats
#pragma unroll
    for (int nt = 0; nt < 8; nt++){
        int c0 = nt*8 + 2*tig;
        float bb0 = b1[c0], bb1 = b1[c0+1];
        float s0 = 0.f, s1v = 0.f, q0 = 0.f, q1v = 0.f;
#pragma unroll
        for (int mt = 0; mt < 2; mt++){
            size_t R = (size_t)m0*32 + w*32 + mt*16 + g;
            float y00 = d[mt][nt].x + bb0, y01 = d[mt][nt].y + bb1;
            float y10 = d[mt][nt].z + bb0, y11 = d[mt][nt].w + bb1;
            *(float2*)&g_Y1[R*64 + c0]     = make_float2(y00, y01);
            *(float2*)&g_Y1[(R+8)*64 + c0] = make_float2(y10, y11);
            s0 += y00 + y10; s1v += y01 + y11;
            q0 += y00*y00 + y10*y10; q1v += y01*y01 + y11*y11;
        }
#pragma unroll
        for (int off = 16; off >= 4; off >>= 1){
            s0  += __shfl_down_sync(0xffffffffu, s0,  off);
            s1v += __shfl_down_sync(0xffffffffu, s1v, off);
            q0  += __shfl_down_sync(0xffffffffu, q0,  off);
            q1v += __shfl_down_sync(0xffffffffu, q1v, off);
        }
        if (g == 0){
            atomicAdd(&ssum[c0], s0);   atomicAdd(&ssum[c0+1], s1v);
            atomicAdd(&ssq[c0],  q0);   atomicAdd(&ssq[c0+1],  q1v);
        }
    }
    __syncthreads();
    if (tid < 64){
        int slot = blockIdx.x & 31;
        atomicAdd(&g_stats[SUM1 + tid*32 + slot], ssum[tid]);
        atomicAdd(&g_stats[SQ1  + tid*32 + slot], ssq[tid]);
    }
}

// ---------------- layer2: tf32 MMA, 64 rows x 128 cols, fused pool ----------------
#define P2 68
__global__ void __launch_bounds__(128) l2_kernel(const float* __restrict__ w2, const float* __restrict__ b2){
    extern __shared__ float smf[];
    uint32_t* xs  = (uint32_t*)smf;        // [64][P2]  (r, k)
    uint32_t* ws  = xs + 64*P2;            // [128][P2] (n, k)
    float* pmax = (float*)(ws + 128*P2);   // [4][128]
    float* pmin = pmax + 4*128;            // [4][128]
    float* ssum = pmin + 4*128;            // 128
    float* ssq  = ssum + 128;              // 128

    int tid = threadIdx.x;
    int w = tid >> 5, lane = tid & 31;
    int g = lane >> 2, tig = lane & 3;
    int m0 = blockIdx.x * 2;

    ssum[tid] = 0.f; ssq[tid] = 0.f;
    for (int i = tid; i < 128*64; i += 128){
        int c = i >> 6, k = i & 63;
        ws[c*P2 + k] = f2tf32(w2[i]);
    }
    for (int i = tid; i < 64*64; i += 128){
        int r = i >> 6, k = i & 63;
        float y = g_Y1[((size_t)m0*32 + r)*64 + k];
        xs[r*P2 + k] = f2tf32(fmaxf(fmaf(g_aff[A1 + k], y, g_aff[C1A + k]), 0.f));
    }
    __syncthreads();

    // warp w: rows [w*16, w*16+16) (1 m-tile), cols 0..127 (16 n-tiles)
    float4 d[16];
#pragma unroll
    for (int nt = 0; nt < 16; nt++) d[nt] = make_float4(0.f,0.f,0.f,0.f);

    int xbase = (w*16 + g)*P2;
    int wbase = g*P2;
#pragma unroll
    for (int kt = 0; kt < 8; kt++){
        int k0 = kt*8 + tig;
        uint32_t a[4];
        a[0] = xs[xbase + k0];
        a[1] = xs[xbase + 8*P2 + k0];
        a[2] = xs[xbase + k0 + 4];
        a[3] = xs[xbase + 8*P2 + k0 + 4];
        uint32_t bf[16][2];
#pragma unroll
        for (int nt = 0; nt < 16; nt++){
            int no = wbase + nt*8*P2;
            bf[nt][0] = ws[no + k0];
            bf[nt][1] = ws[no + k0 + 4];
        }
#pragma unroll
        for (int nt = 0; nt < 16; nt++)
            mma_tf32(d[nt], a, bf[nt]);
    }

    // epilogue: bias, pool max/min over rows, stats
#pragma unroll
    for (int nt = 0; nt < 16; nt++){
        int c0 = nt*8 + 2*tig;
        float bb0 = b2[c0], bb1 = b2[c0+1];
        float y00 = d[nt].x + bb0, y01 = d[nt].y + bb1;
        float y10 = d[nt].z + bb0, y11 = d[nt].w + bb1;
        float mx0 = fmaxf(y00, y10), mx1 = fmaxf(y01, y11);
        float mn0 = fminf(y00, y10), mn1 = fminf(y01, y11);
        float s0 = y00 + y10, s1v = y01 + y11;
        float q0 = y00*y00 + y10*y10, q1v = y01*y01 + y11*y11;
#pragma unroll
        for (int off = 16; off >= 4; off >>= 1){
            mx0 = fmaxf(mx0, __shfl_down_sync(0xffffffffu, mx0, off));
            mx1 = fmaxf(mx1, __shfl_down_sync(0xffffffffu, mx1, off));
            mn0 = fminf(mn0, __shfl_down_sync(0xffffffffu, mn0, off));
            mn1 = fminf(mn1, __shfl_down_sync(0xffffffffu, mn1, off));
            s0  += __shfl_down_sync(0xffffffffu, s0,  off);
            s1v += __shfl_down_sync(0xffffffffu, s1v, off);
            q0  += __shfl_down_sync(0xffffffffu, q0,  off);
            q1v += __shfl_down_sync(0xffffffffu, q1v, off);
        }
        if (g == 0){
            pmax[w*128 + c0] = mx0;  pmax[w*128 + c0+1] = mx1;
            pmin[w*128 + c0] = mn0;  pmin[w*128 + c0+1] = mn1;
            atomicAdd(&ssum[c0], s0);   atomicAdd(&ssum[c0+1], s1v);
            atomicAdd(&ssq[c0],  q0);   atomicAdd(&ssq[c0+1],  q1v);
        }
    }
    __syncthreads();

    for (int i2 = tid; i2 < 256; i2 += 128){
        int cent = i2 >> 7, c = i2 & 127;
        float mx = fmaxf(pmax[(cent*2)*128 + c], pmax[(cent*2+1)*128 + c]);
        float mn = fminf(pmin[(cent*2)*128 + c], pmin[(cent*2+1)*128 + c]);
        g_mx[(size_t)(m0+cent)*128 + c] = mx;
        g_mn[(size_t)(m0+cent)*128 + c] = mn;
    }
    int slot = blockIdx.x & 31;
    atomicAdd(&g_stats[SUM2 + tid*32 + slot], ssum[tid]);
    atomicAdd(&g_stats[SQ2  + tid*32 + slot], ssq[tid]);
}

// ---------------- final: BN2+ReLU on pooled extremum ----------------
__global__ void out_kernel(float* __restrict__ out){
    int i = blockIdx.x*256 + threadIdx.x;   // NCTR_TOT*128
    int c = i & 127;
    float a = g_aff[A2 + c];
    float v = (a >= 0.f) ? g_mx[i] : g_mn[i];
    out[OUT_XYZ_ELEMS + i] = fmaxf(fmaf(a, v, g_aff[C2A + c]), 0.f);
}

// ---------------- host launcher ----------------
extern "C" void kernel_launch(void* const* d_in, const int* in_sizes, int n_in,
                              void* d_out, int out_size){
    const float* xyz   = (const float*)d_in[0];
    const float* feat  = (const float*)d_in[1];
    const float* w0 = (const float*)d_in[2];
    const float* b0 = (const float*)d_in[3];
    const float* g0 = (const float*)d_in[4];
    const float* be0 = (const float*)d_in[5];
    const float* w1 = (const float*)d_in[6];
    const float* b1 = (const float*)d_in[7];
    const float* g1 = (const float*)d_in[8];
    const float* be1 = (const float*)d_in[9];
    const float* w2 = (const float*)d_in[10];
    const float* b2 = (const float*)d_in[11];
    const float* g2 = (const float*)d_in[12];
    const float* be2 = (const float*)d_in[13];
    float* out = (float*)d_out;

    static const int MEGA_SMEM = (12288 + 64) * 4;                         // ~49.4 KB
    static const int L1_SMEM  = (128*P1 + 64*P1)*4 + 128*4 + 128*4;        // ~53.2 KB
    static const int L2_SMEM  = (64*P2 + 128*P2)*4 + 2*4*128*4 + 256*4;    // ~57.3 KB
    cudaFuncSetAttribute(mega_kernel, cudaFuncAttributeMaxDynamicSharedMemorySize, MEGA_SMEM);
    cudaFuncSetAttribute(l1_kernel,  cudaFuncAttributeMaxDynamicSharedMemorySize, L1_SMEM);
    cudaFuncSetAttribute(l2_kernel,  cudaFuncAttributeMaxDynamicSharedMemorySize, L2_SMEM);

    mega_kernel<<<FPS_NB + BATCH*NPTS/4, 256, MEGA_SMEM>>>(xyz, feat, w0, b0, out);
    ballq_kernel<<<NCTR_TOT/8, 256>>>(xyz, out);
    fin_kernel<<<1, 128>>>(g0, be0, SUM0, SQ0, A0, C0A, 64);
    l1_kernel<<<NCTR_TOT/4, 128, L1_SMEM>>>(w1, b1);
    fin_kernel<<<1, 128>>>(g1, be1, SUM1, SQ1, A1, C1A, 64);
    l2_kernel<<<NCTR_TOT/2, 128, L2_SMEM>>>(w2, b2);
    fin_kernel<<<1, 128>>>(g2, be2, SUM2, SQ2, A2, C2A, 128);
    out_kernel<<<NCTR_TOT*128/256, 256>>>(out);
}

// round 6
// speedup vs baseline: 2.0975x; 1.0826x over previous
#include <cuda_runtime.h>
#include <cuda_bf16.h>
#include <math.h>
#include <stdint.h>

// ---------------- problem constants ----------------
#define BATCH 16
#define NPTS 4096
#define NCTR 1024
#define NSAMP 32
#define NROWS (BATCH*NCTR*NSAMP)          // 524288
#define NCTR_TOT (BATCH*NCTR)             // 16384
#define OUT_XYZ_ELEMS (NCTR_TOT*3)        // 49152
#define FPS_NB 16
#define G_NB (BATCH*NPTS/4)               // 16384
#define BQ_NB (NCTR_TOT/8)                // 2048

// stats layout (32 slots per channel, sum then sq)
#define SUM0 0
#define SQ0  (64*32)
#define SUM1 (2*64*32)
#define SQ1  (3*64*32)
#define SUM2 (4*64*32)
#define SQ2  (4*64*32 + 128*32)
#define STATS_TOT (4*64*32 + 2*128*32)    // 16384

// affine layout
#define A0 0
#define C0A 64
#define A1 128
#define C1A 192
#define A2 256
#define C2A 384

// ---------------- scratch (static device memory; no allocs) ----------------
__device__ int   g_fps[NCTR_TOT];
__device__ int   g_bidx[NROWS];
__device__ float g_G[BATCH*NPTS*64];      // 16 MB
__device__ float g_C[NCTR_TOT*64];        // 4 MB
__device__ float g_Y1[NROWS*64];          // 134 MB
__device__ float g_mx[NCTR_TOT*128];      // 8 MB
__device__ float g_mn[NCTR_TOT*128];      // 8 MB
__device__ float g_stats[STATS_TOT];
__device__ float g_aff[512];
__device__ volatile int g_prog[BATCH];

__device__ __forceinline__ unsigned long long u64min(unsigned long long a, unsigned long long b){
    return a < b ? a : b;
}
__device__ __forceinline__ uint32_t f2tf32(float x){
    uint32_t r; asm("cvt.rna.tf32.f32 %0, %1;" : "=r"(r) : "f"(x)); return r;
}
__device__ __forceinline__ void mma_tf32(float4& d, const uint32_t* a, const uint32_t* b){
    asm volatile("mma.sync.aligned.m16n8k8.row.col.f32.tf32.tf32.f32 "
                 "{%0,%1,%2,%3},{%4,%5,%6,%7},{%8,%9},{%0,%1,%2,%3};"
                 : "+f"(d.x),"+f"(d.y),"+f"(d.z),"+f"(d.w)
                 : "r"(a[0]),"r"(a[1]),"r"(a[2]),"r"(a[3]),"r"(b[0]),"r"(b[1]));
}

// =====================================================================
// MEGA: [0,16) FPS  |  [16,16+16384) G (+stats zero)  |  rest: ball query
// =====================================================================
__global__ void __launch_bounds__(256) mega_kernel(
        const float* __restrict__ xyz, const float* __restrict__ feat,
        const float* __restrict__ w0, const float* __restrict__ b0,
        float* __restrict__ out){
    extern __shared__ float sm[];
    int tid = threadIdx.x;
    int bx = blockIdx.x;

    if (bx < FPS_NB){
        // ---------------- FPS ----------------
        float* sx = sm;               // 4096
        float* sy = sm + 4096;
        float* sz = sm + 8192;
        float (*srd)[8] = (float(*)[8])(sm + 12288);   // [2][8]
        int   (*sri)[8] = (int  (*)[8])(sm + 12288 + 16);

        int b = bx;
        const float* xb = xyz + (size_t)b*NPTS*3;
        if (tid == 0) g_prog[b] = 0;

        float px[16], py[16], pz[16], dist[16];
#pragma unroll
        for (int k = 0; k < 16; k++){
            int p = k*256 + tid;
            float x = xb[p*3], y = xb[p*3+1], z = xb[p*3+2];
            px[k]=x; py[k]=y; pz[k]=z; dist[k]=INFINITY;
            sx[p]=x; sy[p]=y; sz[p]=z;
        }
        if (tid == 0) g_fps[b*NCTR] = 0;
        float cx = xb[0], cy = xb[1], cz = xb[2];
        __syncthreads();

        int w = tid >> 5;
        for (int t = 1; t < NCTR; t++){
            float bd = -1.f; int bi = 0;
#pragma unroll
            for (int k = 0; k < 16; k++){
                float dx = px[k]-cx, dy = py[k]-cy, dz = pz[k]-cz;
                float d = fmaf(dx,dx, fmaf(dy,dy, dz*dz));
                float nd = fminf(dist[k], d);
                dist[k] = nd;
                if (nd > bd){ bd = nd; bi = k*256 + tid; }
            }
#pragma unroll
            for (int off = 16; off > 0; off >>= 1){
                float od = __shfl_down_sync(0xffffffffu, bd, off);
                int   oi = __shfl_down_sync(0xffffffffu, bi, off);
                if (od > bd || (od == bd && oi < bi)){ bd = od; bi = oi; }
            }
            int pb = t & 1;
            if ((tid & 31) == 0){ srd[pb][w] = bd; sri[pb][w] = bi; }
            __syncthreads();
            float bd2 = srd[pb][0]; int bi2 = sri[pb][0];
#pragma unroll
            for (int ww = 1; ww < 8; ww++){
                float od = srd[pb][ww]; int oi = sri[pb][ww];
                if (od > bd2 || (od == bd2 && oi < bi2)){ bd2 = od; bi2 = oi; }
            }
            cx = sx[bi2]; cy = sy[bi2]; cz = sz[bi2];
            if (tid == 0){
                g_fps[b*NCTR + t] = bi2;
                if ((t & 31) == 31){ __threadfence(); g_prog[b] = t; }
            }
        }
        __syncthreads();

        // new_xyz gather
        for (int i = tid; i < NCTR; i += 256){
            int idx = g_fps[b*NCTR + i];
            size_t o = (size_t)(b*NCTR + i)*3;
            out[o+0] = sx[idx]; out[o+1] = sy[idx]; out[o+2] = sz[idx];
        }
        __syncthreads();

        // C = new_xyz @ W0xT
        for (int i = tid; i < NCTR*64; i += 256){
            int m = i >> 6, c = i & 63;
            const float* wr = w0 + c*67;
            size_t o = (size_t)(b*NCTR + m)*3;
            float acc = out[o+0]*wr[0];
            acc = fmaf(out[o+1], wr[1], acc);
            acc = fmaf(out[o+2], wr[2], acc);
            g_C[(size_t)(b*NCTR + m)*64 + c] = acc;
        }
    } else if (bx < FPS_NB + G_NB){
        // ---------------- G branch ----------------
        int gb = bx - FPS_NB;
        if (gb < 16){
            for (int i = gb*1024 + tid; i < (gb+1)*1024; i += 256) g_stats[i] = 0.f;
        }
        float* w0s = sm;   // 64*67 floats
        for (int i = tid; i < 64*67; i += 256) w0s[i] = w0[i];
        __syncthreads();
        int p = gb*4 + (tid >> 6);
        int c = tid & 63;
        const float* fr = feat + (size_t)p*64;
        const float* wr = w0s + c*67;
        float acc = b0[c];
        acc = fmaf(xyz[p*3+0], wr[0], acc);
        acc = fmaf(xyz[p*3+1], wr[1], acc);
        acc = fmaf(xyz[p*3+2], wr[2], acc);
#pragma unroll 8
        for (int k = 0; k < 64; k++) acc = fmaf(fr[k], wr[3+k], acc);
        g_G[(size_t)p*64 + c] = acc;
    } else {
        // ---------------- ball query (polls FPS progress) ----------------
        float* sxq = sm;                                      // 1024
        float* syq = sm + 1024;
        float* szq = sm + 2048;
        unsigned long long* cbuf = (unsigned long long*)(sm + 3072);  // [8][256]
        unsigned* usel = (unsigned*)(cbuf + 8*256);           // [8][32]

        int bq = bx - (FPS_NB + G_NB);
        int b = bq >> 7;
        int q = bq & 127;
        int w = tid >> 5, l = tid & 31;
        int m = q*8 + w;
        int gm = b*NCTR + m;

        if (tid == 0){
            int need = q*8 + 7;
            while (g_prog[b] < need) __nanosleep(128);
            __threadfence();
        }
        __syncthreads();

        int cidx = g_fps[gm];
        const float* xb = xyz + (size_t)b*NPTS*3;
        float qx = xb[cidx*3], qy = xb[cidx*3+1], qz = xb[cidx*3+2];
        const float R2v = (float)(0.2*0.2);

        unsigned long long minkey = ~0ull;
        int cnt = 0;

        for (int ch = 0; ch < 4; ch++){
            __syncthreads();
            for (int i = tid; i < 1024; i += 256){
                int p = ch*1024 + i;
                sxq[i] = xb[p*3]; syq[i] = xb[p*3+1]; szq[i] = xb[p*3+2];
            }
            __syncthreads();
            for (int j = 0; j < 32; j++){
                int pl = j*32 + l;
                float dx = qx - sxq[pl], dy = qy - syq[pl], dz = qz - szq[pl];
                float d = fmaf(dx,dx, fmaf(dy,dy, dz*dz));
                int p = ch*1024 + pl;
                unsigned long long key = ((unsigned long long)__float_as_uint(d) << 32) | (unsigned)p;
                minkey = u64min(minkey, key);
                bool in = (d <= R2v);
                unsigned mask = __ballot_sync(0xffffffffu, in);
                if (in){
                    int pos = cnt + __popc(mask & ((1u << l) - 1u));
                    if (pos < 256) cbuf[w*256 + pos] = key;
                }
                cnt += __popc(mask);
            }
        }
#pragma unroll
        for (int off = 16; off > 0; off >>= 1)
            minkey = u64min(minkey, __shfl_down_sync(0xffffffffu, minkey, off));
        minkey = __shfl_sync(0xffffffffu, minkey, 0);
        unsigned fill = (unsigned)minkey;

        if (cnt <= 32){
            unsigned v = (l < cnt) ? (unsigned)cbuf[w*256 + l] : fill;
            usel[w*32 + l] = v;
        } else {
            int n = cnt < 256 ? cnt : 256;
            unsigned long long e[8];
#pragma unroll
            for (int qq = 0; qq < 8; qq++){ int p = qq*32 + l; e[qq] = (p < n) ? cbuf[w*256 + p] : ~0ull; }
            for (int r = 0; r < 32; r++){
                unsigned long long loc = ~0ull;
#pragma unroll
                for (int qq = 0; qq < 8; qq++) loc = u64min(loc, e[qq]);
#pragma unroll
                for (int off = 16; off > 0; off >>= 1)
                    loc = u64min(loc, __shfl_down_sync(0xffffffffu, loc, off));
                loc = __shfl_sync(0xffffffffu, loc, 0);
                if (l == r) usel[w*32 + r] = (unsigned)loc;
#pragma unroll
                for (int qq = 0; qq < 8; qq++) if (e[qq] == loc) e[qq] = ~0ull;
            }
        }
        __syncwarp();
        g_bidx[gm*32 + l] = (int)usel[w*32 + l];
    }
}

// ---------------- BN0 stats (after mega: g_G, g_C, g_bidx all ready) ----------------
__global__ void __launch_bounds__(256) stats0_kernel(){
    __shared__ float ssum[64], ssq[64];
    int tid = threadIdx.x, w = tid >> 5, l = tid & 31;
    int gm = blockIdx.x*8 + w;
    int b = gm >> 10;
    if (tid < 64){ ssum[tid] = 0.f; ssq[tid] = 0.f; }
    __syncthreads();

    int sel = g_bidx[gm*32 + l];
    float Cc1 = g_C[gm*64 + l], Cc2 = g_C[gm*64 + 32 + l];
    const float* Gb = g_G + (size_t)b*NPTS*64;
    float s1 = 0.f, q1 = 0.f, s2 = 0.f, q2 = 0.f;
#pragma unroll 4
    for (int s = 0; s < 32; s++){
        int ip = __shfl_sync(0xffffffffu, sel, s);
        float ga = Gb[(size_t)ip*64 + l] - Cc1;
        float gb2 = Gb[(size_t)ip*64 + 32 + l] - Cc2;
        s1 += ga; q1 = fmaf(ga, ga, q1);
        s2 += gb2; q2 = fmaf(gb2, gb2, q2);
    }
    atomicAdd(&ssum[l], s1);      atomicAdd(&ssq[l], q1);
    atomicAdd(&ssum[32+l], s2);   atomicAdd(&ssq[32+l], q2);
    __syncthreads();
    if (tid < 64){
        int slot = blockIdx.x & 31;
        atomicAdd(&g_stats[SUM0 + tid*32 + slot], ssum[tid]);
        atomicAdd(&g_stats[SQ0  + tid*32 + slot], ssq[tid]);
    }
}

// ---------------- BN finalize ----------------
__global__ void fin_kernel(const float* __restrict__ gamma, const float* __restrict__ beta,
                           int sumoff, int sqoff, int aoff, int coff, int nch){
    int c = threadIdx.x;
    if (c >= nch) return;
    float s = 0.f, q = 0.f;
    for (int j = 0; j < 32; j++){ s += g_stats[sumoff + c*32 + j]; q += g_stats[sqoff + c*32 + j]; }
    const float invN = 1.f / (float)NROWS;
    float mean = s * invN;
    float var = q * invN - mean*mean;
    float rstd = rsqrtf(var + 1e-5f);
    float a = gamma[c] * rstd;
    g_aff[aoff + c] = a;
    g_aff[coff + c] = beta[c] - mean * a;
}

// ---------------- layer1: tf32 MMA, 256 thr, 128 rows x 64 cols ----------------
#define P1 68
__global__ void __launch_bounds__(256) l1_kernel(const float* __restrict__ w1, const float* __restrict__ b1){
    extern __shared__ float smf[];
    uint32_t* xs = (uint32_t*)smf;        // [128][P1] (r,k)
    uint32_t* ws = xs + 128*P1;           // [64][P1]  (n,k)
    int*   sidx = (int*)(ws + 64*P1);     // 128
    float* ssum = (float*)(sidx + 128);   // 64
    float* ssq  = ssum + 64;              // 64

    int tid = threadIdx.x;
    int w = tid >> 5, lane = tid & 31;
    int g = lane >> 2, tig = lane & 3;
    int wr = w >> 1, wc = w & 1;          // row-tile 0..3, col-tile 0..1
    int m0 = blockIdx.x * 4;
    int b = m0 >> 10;

    if (tid < 64){ ssum[tid] = 0.f; ssq[tid] = 0.f; }
    if (tid < 128) sidx[tid] = g_bidx[m0*32 + tid];
    for (int i = tid; i < 64*64; i += 256){
        int c = i >> 6, k = i & 63;
        ws[c*P1 + k] = f2tf32(w1[i]);
    }
    __syncthreads();

    const float* Gb = g_G + (size_t)b*NPTS*64;
#pragma unroll 8
    for (int e = 0; e < 32; e++){
        int flat = e*256 + tid;
        int r = flat >> 6, c = flat & 63;
        int gm = m0 + (r >> 5);
        float y = Gb[(size_t)sidx[r]*64 + c] - g_C[gm*64 + c];
        xs[r*P1 + c] = f2tf32(fmaxf(fmaf(g_aff[A0 + c], y, g_aff[C0A + c]), 0.f));
    }
    __syncthreads();

    float4 d[2][4];
#pragma unroll
    for (int mt = 0; mt < 2; mt++)
#pragma unroll
        for (int nt = 0; nt < 4; nt++) d[mt][nt] = make_float4(0.f,0.f,0.f,0.f);

    int xbase = (wr*32 + g)*P1;
    int wbase = (wc*32 + g)*P1;
#pragma unroll
    for (int kt = 0; kt < 8; kt++){
        int k0 = kt*8 + tig;
        uint32_t a[2][4];
#pragma unroll
        for (int mt = 0; mt < 2; mt++){
            int ro = xbase + mt*16*P1;
            a[mt][0] = xs[ro + k0];
            a[mt][1] = xs[ro + 8*P1 + k0];
            a[mt][2] = xs[ro + k0 + 4];
            a[mt][3] = xs[ro + 8*P1 + k0 + 4];
        }
        uint32_t bf[4][2];
#pragma unroll
        for (int nt = 0; nt < 4; nt++){
            int no = wbase + nt*8*P1;
            bf[nt][0] = ws[no + k0];
            bf[nt][1] = ws[no + k0 + 4];
        }
#pragma unroll
        for (int nt = 0; nt < 4; nt++)
#pragma unroll
            for (int mt = 0; mt < 2; mt++)
                mma_tf32(d[mt][nt], a[mt], bf[nt]);
    }

    // epilogue: bias, store Y1, stats
#pragma unroll
    for (int nt = 0; nt < 4; nt++){
        int c0 = wc*32 + nt*8 + 2*tig;
        float bb0 = b1[c0], bb1 = b1[c0+1];
        float s0 = 0.f, s1v = 0.f, q0 = 0.f, q1v = 0.f;
#pragma unroll
        for (int mt = 0; mt < 2; mt++){
            size_t R = (size_t)m0*32 + wr*32 + mt*16 + g;
            float y00 = d[mt][nt].x + bb0, y01 = d[mt][nt].y + bb1;
            float y10 = d[mt][nt].z + bb0, y11 = d[mt][nt].w + bb1;
            *(float2*)&g_Y1[R*64 + c0]     = make_float2(y00, y01);
            *(float2*)&g_Y1[(R+8)*64 + c0] = make_float2(y10, y11);
            s0 += y00 + y10; s1v += y01 + y11;
            q0 += y00*y00 + y10*y10; q1v += y01*y01 + y11*y11;
        }
#pragma unroll
        for (int off = 16; off >= 4; off >>= 1){
            s0  += __shfl_down_sync(0xffffffffu, s0,  off);
            s1v += __shfl_down_sync(0xffffffffu, s1v, off);
            q0  += __shfl_down_sync(0xffffffffu, q0,  off);
            q1v += __shfl_down_sync(0xffffffffu, q1v, off);
        }
        if (g == 0){
            atomicAdd(&ssum[c0], s0);   atomicAdd(&ssum[c0+1], s1v);
            atomicAdd(&ssq[c0],  q0);   atomicAdd(&ssq[c0+1],  q1v);
        }
    }
    __syncthreads();
    if (tid < 64){
        int slot = blockIdx.x & 31;
        atomicAdd(&g_stats[SUM1 + tid*32 + slot], ssum[tid]);
        atomicAdd(&g_stats[SQ1  + tid*32 + slot], ssq[tid]);
    }
}

// ---------------- layer2: tf32 MMA, 256 thr, 64 rows x 128 cols, fused pool ----------------
#define P2 68
__global__ void __launch_bounds__(256) l2_kernel(const float* __restrict__ w2, const float* __restrict__ b2){
    extern __shared__ float smf[];
    uint32_t* xs  = (uint32_t*)smf;        // [64][P2]  (r,k)
    uint32_t* ws  = xs + 64*P2;            // [128][P2] (n,k)
    float* ssum = (float*)(ws + 128*P2);   // 128
    float* ssq  = ssum + 128;              // 128

    int tid = threadIdx.x;
    int w = tid >> 5, lane = tid & 31;
    int g = lane >> 2, tig = lane & 3;
    int wr = w >> 2, wc = w & 3;           // row-tile 0..1 (one center each), col-tile 0..3
    int m0 = blockIdx.x * 2;

    if (tid < 128){ ssum[tid] = 0.f; ssq[tid] = 0.f; }
    for (int i = tid; i < 128*64; i += 256){
        int c = i >> 6, k = i & 63;
        ws[c*P2 + k] = f2tf32(w2[i]);
    }
    for (int i = tid; i < 64*64; i += 256){
        int r = i >> 6, k = i & 63;
        float y = g_Y1[((size_t)m0*32 + r)*64 + k];
        xs[r*P2 + k] = f2tf32(fmaxf(fmaf(g_aff[A1 + k], y, g_aff[C1A + k]), 0.f));
    }
    __syncthreads();

    float4 d[2][4];
#pragma unroll
    for (int mt = 0; mt < 2; mt++)
#pragma unroll
        for (int nt = 0; nt < 4; nt++) d[mt][nt] = make_float4(0.f,0.f,0.f,0.f);

    int xbase = (wr*32 + g)*P2;
    int wbase = (wc*32 + g)*P2;
#pragma unroll
    for (int kt = 0; kt < 8; kt++){
        int k0 = kt*8 + tig;
        uint32_t a[2][4];
#pragma unroll
        for (int mt = 0; mt < 2; mt++){
            int ro = xbase + mt*16*P2;
            a[mt][0] = xs[ro + k0];
            a[mt][1] = xs[ro + 8*P2 + k0];
            a[mt][2] = xs[ro + k0 + 4];
            a[mt][3] = xs[ro + 8*P2 + k0 + 4];
        }
        uint32_t bf[4][2];
#pragma unroll
        for (int nt = 0; nt < 4; nt++){
            int no = wbase + nt*8*P2;
            bf[nt][0] = ws[no + k0];
            bf[nt][1] = ws[no + k0 + 4];
        }
#pragma unroll
        for (int nt = 0; nt < 4; nt++)
#pragma unroll
            for (int mt = 0; mt < 2; mt++)
                mma_tf32(d[mt][nt], a[mt], bf[nt]);
    }

    // epilogue: bias, pool over center rows (all within this warp), stats
    int cent = m0 + wr;
#pragma unroll
    for (int nt = 0; nt < 4; nt++){
        int c0 = wc*32 + nt*8 + 2*tig;
        float bb0 = b2[c0], bb1 = b2[c0+1];
        float y00a = d[0][nt].x + bb0, y01a = d[0][nt].y + bb1;
        float y10a = d[0][nt].z + bb0, y11a = d[0][nt].w + bb1;
        float y00b = d[1][nt].x + bb0, y01b = d[1][nt].y + bb1;
        float y10b = d[1][nt].z + bb0, y11b = d[1][nt].w + bb1;
        float mx0 = fmaxf(fmaxf(y00a, y10a), fmaxf(y00b, y10b));
        float mx1 = fmaxf(fmaxf(y01a, y11a), fmaxf(y01b, y11b));
        float mn0 = fminf(fminf(y00a, y10a), fminf(y00b, y10b));
        float mn1 = fminf(fminf(y01a, y11a), fminf(y01b, y11b));
        float s0 = y00a + y10a + y00b + y10b;
        float s1v = y01a + y11a + y01b + y11b;
        float q0 = y00a*y00a + y10a*y10a + y00b*y00b + y10b*y10b;
        float q1v = y01a*y01a + y11a*y11a + y01b*y01b + y11b*y11b;
#pragma unroll
        for (int off = 16; off >= 4; off >>= 1){
            mx0 = fmaxf(mx0, __shfl_down_sync(0xffffffffu, mx0, off));
            mx1 = fmaxf(mx1, __shfl_down_sync(0xffffffffu, mx1, off));
            mn0 = fminf(mn0, __shfl_down_sync(0xffffffffu, mn0, off));
            mn1 = fminf(mn1, __shfl_down_sync(0xffffffffu, mn1, off));
            s0  += __shfl_down_sync(0xffffffffu, s0,  off);
            s1v += __shfl_down_sync(0xffffffffu, s1v, off);
            q0  += __shfl_down_sync(0xffffffffu, q0,  off);
            q1v += __shfl_down_sync(0xffffffffu, q1v, off);
        }
        if (g == 0){
            g_mx[(size_t)cent*128 + c0]   = mx0;
            g_mx[(size_t)cent*128 + c0+1] = mx1;
            g_mn[(size_t)cent*128 + c0]   = mn0;
            g_mn[(size_t)cent*128 + c0+1] = mn1;
            atomicAdd(&ssum[c0], s0);   atomicAdd(&ssum[c0+1], s1v);
            atomicAdd(&ssq[c0],  q0);   atomicAdd(&ssq[c0+1],  q1v);
        }
    }
    __syncthreads();
    if (tid < 128){
        int slot = blockIdx.x & 31;
        atomicAdd(&g_stats[SUM2 + tid*32 + slot], ssum[tid]);
        atomicAdd(&g_stats[SQ2  + tid*32 + slot], ssq[tid]);
    }
}

// ---------------- final: BN2+ReLU on pooled extremum ----------------
__global__ void out_kernel(float* __restrict__ out){
    int i = blockIdx.x*256 + threadIdx.x;   // NCTR_TOT*128
    int c = i & 127;
    float a = g_aff[A2 + c];
    float v = (a >= 0.f) ? g_mx[i] : g_mn[i];
    out[OUT_XYZ_ELEMS + i] = fmaxf(fmaf(a, v, g_aff[C2A + c]), 0.f);
}

// ---------------- host launcher ----------------
extern "C" void kernel_launch(void* const* d_in, const int* in_sizes, int n_in,
                              void* d_out, int out_size){
    const float* xyz   = (const float*)d_in[0];
    const float* feat  = (const float*)d_in[1];
    const float* w0 = (const float*)d_in[2];
    const float* b0 = (const float*)d_in[3];
    const float* g0 = (const float*)d_in[4];
    const float* be0 = (const float*)d_in[5];
    const float* w1 = (const float*)d_in[6];
    const float* b1 = (const float*)d_in[7];
    const float* g1 = (const float*)d_in[8];
    const float* be1 = (const float*)d_in[9];
    const float* w2 = (const float*)d_in[10];
    const float* b2 = (const float*)d_in[11];
    const float* g2 = (const float*)d_in[12];
    const float* be2 = (const float*)d_in[13];
    float* out = (float*)d_out;

    static const int MEGA_SMEM = (12288 + 64) * 4;                      // ~49.4 KB
    static const int L1_SMEM  = (128*P1 + 64*P1)*4 + 128*4 + 128*4;     // ~53.2 KB
    static const int L2_SMEM  = (64*P2 + 128*P2)*4 + 256*4;             // ~53.2 KB
    cudaFuncSetAttribute(mega_kernel, cudaFuncAttributeMaxDynamicSharedMemorySize, MEGA_SMEM);
    cudaFuncSetAttribute(l1_kernel,  cudaFuncAttributeMaxDynamicSharedMemorySize, L1_SMEM);
    cudaFuncSetAttribute(l2_kernel,  cudaFuncAttributeMaxDynamicSharedMemorySize, L2_SMEM);

    mega_kernel<<<FPS_NB + G_NB + BQ_NB, 256, MEGA_SMEM>>>(xyz, feat, w0, b0, out);
    stats0_kernel<<<BQ_NB, 256>>>();
    fin_kernel<<<1, 128>>>(g0, be0, SUM0, SQ0, A0, C0A, 64);
    l1_kernel<<<NCTR_TOT/4, 256, L1_SMEM>>>(w1, b1);
    fin_kernel<<<1, 128>>>(g1, be1, SUM1, SQ1, A1, C1A, 64);
    l2_kernel<<<NCTR_TOT/2, 256, L2_SMEM>>>(w2, b2);
    fin_kernel<<<1, 128>>>(g2, be2, SUM2, SQ2, A2, C2A, 128);
    out_kernel<<<NCTR_TOT*128/256, 256>>>(out);
}

// round 7
// speedup vs baseline: 2.3239x; 1.1080x over previous
#include <cuda_runtime.h>
#include <cuda_bf16.h>
#include <math.h>
#include <stdint.h>

// ---------------- problem constants ----------------
#define BATCH 16
#define NPTS 4096
#define NCTR 1024
#define NSAMP 32
#define NROWS (BATCH*NCTR*NSAMP)          // 524288
#define NCTR_TOT (BATCH*NCTR)             // 16384
#define OUT_XYZ_ELEMS (NCTR_TOT*3)        // 49152
#define FPS_NB 16
#define G_NB (BATCH*NPTS/4)               // 16384
#define BQ_NB (NCTR_TOT/8)                // 2048

// stats layout (32 slots per channel, sum then sq)
#define SUM0 0
#define SQ0  (64*32)
#define SUM1 (2*64*32)
#define SQ1  (3*64*32)
#define SUM2 (4*64*32)
#define SQ2  (4*64*32 + 128*32)
#define STATS_TOT (4*64*32 + 2*128*32)    // 16384

// affine layout
#define A0 0
#define C0A 64
#define A1 128
#define C1A 192
#define A2 256
#define C2A 384

// ---------------- scratch (static device memory; no allocs) ----------------
__device__ int   g_fps[NCTR_TOT];
__device__ int   g_bidx[NROWS];
__device__ float g_G[BATCH*NPTS*64];      // 16 MB
__device__ float g_C[NCTR_TOT*64];        // 4 MB
__device__ float g_Y1[NROWS*64];          // 134 MB
__device__ float g_mx[NCTR_TOT*128];      // 8 MB
__device__ float g_mn[NCTR_TOT*128];      // 8 MB
__device__ float g_stats[STATS_TOT];
__device__ float g_aff[512];
__device__ volatile int g_prog[BATCH];    // FPS progress (monotone across replays)
__device__ int g_gcnt[BATCH];             // G-completion counter (monotone)

__device__ __forceinline__ unsigned long long u64min(unsigned long long a, unsigned long long b){
    return a < b ? a : b;
}
__device__ __forceinline__ uint32_t f2tf32(float x){
    uint32_t r; asm("cvt.rna.tf32.f32 %0, %1;" : "=r"(r) : "f"(x)); return r;
}
__device__ __forceinline__ void mma_tf32(float4& d, const uint32_t* a, const uint32_t* b){
    asm volatile("mma.sync.aligned.m16n8k8.row.col.f32.tf32.tf32.f32 "
                 "{%0,%1,%2,%3},{%4,%5,%6,%7},{%8,%9},{%0,%1,%2,%3};"
                 : "+f"(d.x),"+f"(d.y),"+f"(d.z),"+f"(d.w)
                 : "r"(a[0]),"r"(a[1]),"r"(a[2]),"r"(a[3]),"r"(b[0]),"r"(b[1]));
}
// packed f32x2 helpers
__device__ __forceinline__ unsigned long long pk2(float lo, float hi){
    unsigned long long r; asm("mov.b64 %0,{%1,%2};" : "=l"(r) : "f"(lo), "f"(hi)); return r;
}
__device__ __forceinline__ void unpk2(unsigned long long v, float& lo, float& hi){
    asm("mov.b64 {%0,%1},%2;" : "=f"(lo), "=f"(hi) : "l"(v));
}
__device__ __forceinline__ unsigned long long add2(unsigned long long a, unsigned long long b){
    unsigned long long r; asm("add.rn.f32x2 %0,%1,%2;" : "=l"(r) : "l"(a), "l"(b)); return r;
}
__device__ __forceinline__ unsigned long long mul2(unsigned long long a, unsigned long long b){
    unsigned long long r; asm("mul.rn.f32x2 %0,%1,%2;" : "=l"(r) : "l"(a), "l"(b)); return r;
}
__device__ __forceinline__ unsigned long long fma2(unsigned long long a, unsigned long long b, unsigned long long c){
    unsigned long long r; asm("fma.rn.f32x2 %0,%1,%2,%3;" : "=l"(r) : "l"(a), "l"(b), "l"(c)); return r;
}
// k-pair permutation: within each group of 8 k's, place (k, k+4) adjacently
__device__ __forceinline__ int kperm(int k){
    return (k & ~7) | ((k & 3) << 1) | ((k >> 2) & 1);
}

// =====================================================================
// MEGA: [0,16) FPS  |  [16,16+16384) G (+stats zero)  |  rest: ballq+BN0 stats
// =====================================================================
__global__ void __launch_bounds__(256) mega_kernel(
        const float* __restrict__ xyz, const float* __restrict__ feat,
        const float* __restrict__ w0, const float* __restrict__ b0,
        float* __restrict__ out){
    extern __shared__ float sm[];
    int tid = threadIdx.x;
    int bx = blockIdx.x;

    if (bx < FPS_NB){
        // ---------------- FPS ----------------
        float* sx = sm;               // 4096
        float* sy = sm + 4096;
        float* sz = sm + 8192;
        float (*srd)[8] = (float(*)[8])(sm + 12288);   // [2][8]
        int*   s_idx    = (int*)(sm + 12288 + 16);     // [2]

        int b = bx;
        const float* xb = xyz + (size_t)b*NPTS*3;

        float px[16], py[16], pz[16], dist[16];
#pragma unroll
        for (int k = 0; k < 16; k++){
            int p = k*256 + tid;
            float x = xb[p*3], y = xb[p*3+1], z = xb[p*3+2];
            px[k]=x; py[k]=y; pz[k]=z; dist[k]=INFINITY;
            sx[p]=x; sy[p]=y; sz[p]=z;
        }
        unsigned long long px2[8], py2[8], pz2[8];
#pragma unroll
        for (int j = 0; j < 8; j++){
            px2[j] = pk2(px[2*j], px[2*j+1]);
            py2[j] = pk2(py[2*j], py[2*j+1]);
            pz2[j] = pk2(pz[2*j], pz[2*j+1]);
        }
        if (tid == 0){ g_fps[b*NCTR] = 0; s_idx[0] = 0x7fffffff; s_idx[1] = 0x7fffffff; }
        float cx = xb[0], cy = xb[1], cz = xb[2];
        __syncthreads();

        int w = tid >> 5;
        for (int t = 1; t < NCTR; t++){
            unsigned long long ncx = pk2(-cx,-cx), ncy = pk2(-cy,-cy), ncz = pk2(-cz,-cz);
            float m = -1.f;
#pragma unroll
            for (int j = 0; j < 8; j++){
                unsigned long long dx = add2(px2[j], ncx);
                unsigned long long dy = add2(py2[j], ncy);
                unsigned long long dz = add2(pz2[j], ncz);
                unsigned long long dd = fma2(dx, dx, fma2(dy, dy, mul2(dz, dz)));
                float dlo, dhi; unpk2(dd, dlo, dhi);
                dist[2*j]   = fminf(dist[2*j],   dlo);
                dist[2*j+1] = fminf(dist[2*j+1], dhi);
                m = fmaxf(m, fmaxf(dist[2*j], dist[2*j+1]));
            }
            // warp max (value only)
            float wm = m;
#pragma unroll
            for (int off = 16; off > 0; off >>= 1)
                wm = fmaxf(wm, __shfl_down_sync(0xffffffffu, wm, off));
            int pb = t & 1;
            if ((tid & 31) == 0) srd[pb][w] = wm;
            __syncthreads();
            float bm = srd[pb][0];
#pragma unroll
            for (int ww = 1; ww < 8; ww++) bm = fmaxf(bm, srd[pb][ww]);
            if (tid == 0) s_idx[1 - pb] = 0x7fffffff;   // reset other buffer for next iter
            if (m == bm){
                int cand = 0x7fffffff;
#pragma unroll
                for (int k = 15; k >= 0; k--)
                    if (dist[k] == bm) cand = k*256 + tid;
                atomicMin(&s_idx[pb], cand);
            }
            __syncthreads();
            int bi2 = s_idx[pb];
            cx = sx[bi2]; cy = sy[bi2]; cz = sz[bi2];
            if (tid == 0){
                g_fps[b*NCTR + t] = bi2;
                if ((t & 31) == 31){ __threadfence(); g_prog[b] = t; }
            }
        }
        __syncthreads();

        // new_xyz gather
        for (int i = tid; i < NCTR; i += 256){
            int idx = g_fps[b*NCTR + i];
            size_t o = (size_t)(b*NCTR + i)*3;
            out[o+0] = sx[idx]; out[o+1] = sy[idx]; out[o+2] = sz[idx];
        }
        __syncthreads();

        // C = new_xyz @ W0xT  (used by l1)
        for (int i = tid; i < NCTR*64; i += 256){
            int m2 = i >> 6, c = i & 63;
            const float* wr = w0 + c*67;
            size_t o = (size_t)(b*NCTR + m2)*3;
            float acc = out[o+0]*wr[0];
            acc = fmaf(out[o+1], wr[1], acc);
            acc = fmaf(out[o+2], wr[2], acc);
            g_C[(size_t)(b*NCTR + m2)*64 + c] = acc;
        }
    } else if (bx < FPS_NB + G_NB){
        // ---------------- G branch ----------------
        int gb = bx - FPS_NB;
        if (gb < 16){
            for (int i = gb*1024 + tid; i < (gb+1)*1024; i += 256) g_stats[i] = 0.f;
        }
        float* w0s = sm;   // 64*67 floats
        for (int i = tid; i < 64*67; i += 256) w0s[i] = w0[i];
        __syncthreads();
        int p = gb*4 + (tid >> 6);
        int c = tid & 63;
        const float* fr = feat + (size_t)p*64;
        const float* wr = w0s + c*67;
        float acc = b0[c];
        acc = fmaf(xyz[p*3+0], wr[0], acc);
        acc = fmaf(xyz[p*3+1], wr[1], acc);
        acc = fmaf(xyz[p*3+2], wr[2], acc);
#pragma unroll 8
        for (int k = 0; k < 64; k++) acc = fmaf(fr[k], wr[3+k], acc);
        g_G[(size_t)p*64 + c] = acc;
        __syncthreads();
        if (tid == 0){
            __threadfence();
            atomicAdd(&g_gcnt[gb >> 10], 1);
        }
    } else {
        // ---------------- ball query + BN0 stats (polls FPS/G progress) ----------------
        float* sxq = sm;                                      // 1024
        float* syq = sm + 1024;
        float* szq = sm + 2048;
        unsigned long long* cbuf = (unsigned long long*)(sm + 3072);  // [8][256]
        unsigned* usel = (unsigned*)(sm + 7168);              // [8][32]
        float* ssum = sm + 7424;                              // 64
        float* ssq  = sm + 7488;                              // 64

        int bq = bx - (FPS_NB + G_NB);
        int b = bq >> 7;
        int q = bq & 127;
        int w = tid >> 5, l = tid & 31;
        int m = q*8 + w;
        int gm = b*NCTR + m;

        if (tid == 0){
            int need = q*8 + 7;
            while (g_prog[b] < need) __nanosleep(128);
            __threadfence();
        }
        __syncthreads();

        int cidx = g_fps[gm];
        const float* xb = xyz + (size_t)b*NPTS*3;
        float qx = xb[cidx*3], qy = xb[cidx*3+1], qz = xb[cidx*3+2];
        const float R2v = (float)(0.2*0.2);

        unsigned long long minkey = ~0ull;
        int cnt = 0;

        for (int ch = 0; ch < 4; ch++){
            __syncthreads();
            for (int i = tid; i < 1024; i += 256){
                int p = ch*1024 + i;
                sxq[i] = xb[p*3]; syq[i] = xb[p*3+1]; szq[i] = xb[p*3+2];
            }
            __syncthreads();
            for (int j = 0; j < 32; j++){
                int pl = j*32 + l;
                float dx = qx - sxq[pl], dy = qy - syq[pl], dz = qz - szq[pl];
                float d = fmaf(dx,dx, fmaf(dy,dy, dz*dz));
                int p = ch*1024 + pl;
                unsigned long long key = ((unsigned long long)__float_as_uint(d) << 32) | (unsigned)p;
                minkey = u64min(minkey, key);
                bool in = (d <= R2v);
                unsigned mask = __ballot_sync(0xffffffffu, in);
                if (in){
                    int pos = cnt + __popc(mask & ((1u << l) - 1u));
                    if (pos < 256) cbuf[w*256 + pos] = key;
                }
                cnt += __popc(mask);
            }
        }
#pragma unroll
        for (int off = 16; off > 0; off >>= 1)
            minkey = u64min(minkey, __shfl_down_sync(0xffffffffu, minkey, off));
        minkey = __shfl_sync(0xffffffffu, minkey, 0);
        unsigned fill = (unsigned)minkey;

        if (cnt <= 32){
            unsigned v = (l < cnt) ? (unsigned)cbuf[w*256 + l] : fill;
            usel[w*32 + l] = v;
        } else {
            int n = cnt < 256 ? cnt : 256;
            unsigned long long e[8];
#pragma unroll
            for (int qq = 0; qq < 8; qq++){ int p = qq*32 + l; e[qq] = (p < n) ? cbuf[w*256 + p] : ~0ull; }
            for (int r = 0; r < 32; r++){
                unsigned long long loc = ~0ull;
#pragma unroll
                for (int qq = 0; qq < 8; qq++) loc = u64min(loc, e[qq]);
#pragma unroll
                for (int off = 16; off > 0; off >>= 1)
                    loc = u64min(loc, __shfl_down_sync(0xffffffffu, loc, off));
                loc = __shfl_sync(0xffffffffu, loc, 0);
                if (l == r) usel[w*32 + r] = (unsigned)loc;
#pragma unroll
                for (int qq = 0; qq < 8; qq++) if (e[qq] == loc) e[qq] = ~0ull;
            }
        }
        __syncwarp();
        g_bidx[gm*32 + l] = (int)usel[w*32 + l];

        // -------- BN0 stats (needs full g_G for this batch) --------
        __syncthreads();
        if (tid < 64){ ssum[tid] = 0.f; ssq[tid] = 0.f; }
        if (tid == 0){
            while (*((volatile int*)&g_gcnt[b]) < 1024) __nanosleep(64);
            __threadfence();
        }
        __syncthreads();

        // center projection (bit-identical to c_kernel arithmetic)
        const float* wrA = w0 + l*67;
        const float* wrB = w0 + (32 + l)*67;
        float Cc1 = qx*wrA[0]; Cc1 = fmaf(qy, wrA[1], Cc1); Cc1 = fmaf(qz, wrA[2], Cc1);
        float Cc2 = qx*wrB[0]; Cc2 = fmaf(qy, wrB[1], Cc2); Cc2 = fmaf(qz, wrB[2], Cc2);

        const float* Gb = g_G + (size_t)b*NPTS*64;
        float s1 = 0.f, q1 = 0.f, s2 = 0.f, q2 = 0.f;
        for (int s = 0; s < 32; s++){
            unsigned ip = usel[w*32 + s];
            float ga  = Gb[(size_t)ip*64 + l] - Cc1;
            float gb2 = Gb[(size_t)ip*64 + 32 + l] - Cc2;
            s1 += ga;  q1 = fmaf(ga, ga, q1);
            s2 += gb2; q2 = fmaf(gb2, gb2, q2);
        }
        atomicAdd(&ssum[l], s1);      atomicAdd(&ssq[l], q1);
        atomicAdd(&ssum[32+l], s2);   atomicAdd(&ssq[32+l], q2);
        __syncthreads();
        if (tid < 64){
            int slot = bq & 31;
            atomicAdd(&g_stats[SUM0 + tid*32 + slot], ssum[tid]);
            atomicAdd(&g_stats[SQ0  + tid*32 + slot], ssq[tid]);
        }
    }
}

// ---------------- BN finalize ----------------
__global__ void fin_kernel(const float* __restrict__ gamma, const float* __restrict__ beta,
                           int sumoff, int sqoff, int aoff, int coff, int nch){
    int c = threadIdx.x;
    if (c >= nch) return;
    float s = 0.f, q = 0.f;
    for (int j = 0; j < 32; j++){ s += g_stats[sumoff + c*32 + j]; q += g_stats[sqoff + c*32 + j]; }
    const float invN = 1.f / (float)NROWS;
    float mean = s * invN;
    float var = q * invN - mean*mean;
    float rstd = rsqrtf(var + 1e-5f);
    float a = gamma[c] * rstd;
    g_aff[aoff + c] = a;
    g_aff[coff + c] = beta[c] - mean * a;
}

// ---------------- layer1: tf32 MMA, 256 thr, 128 rows x 64 cols ----------------
#define P1 68
__global__ void __launch_bounds__(256) l1_kernel(const float* __restrict__ w1, const float* __restrict__ b1){
    extern __shared__ float smf[];
    uint32_t* xs = (uint32_t*)smf;        // [128][P1] (r, kperm)
    uint32_t* ws = xs + 128*P1;           // [64][P1]  (n, kperm)
    int*   sidx = (int*)(ws + 64*P1);     // 128
    float* ssum = (float*)(sidx + 128);   // 64
    float* ssq  = ssum + 64;              // 64

    int tid = threadIdx.x;
    int w = tid >> 5, lane = tid & 31;
    int g = lane >> 2, tig = lane & 3;
    int wr = w >> 1, wc = w & 1;          // row-tile 0..3, col-tile 0..1
    int m0 = blockIdx.x * 4;
    int b = m0 >> 10;

    if (tid < 64){ ssum[tid] = 0.f; ssq[tid] = 0.f; }
    if (tid < 128) sidx[tid] = g_bidx[m0*32 + tid];
    for (int i = tid; i < 64*64; i += 256){
        int c = i >> 6, k = i & 63;
        ws[c*P1 + kperm(k)] = f2tf32(w1[i]);
    }
    __syncthreads();

    const float* Gb = g_G + (size_t)b*NPTS*64;
#pragma unroll 8
    for (int e = 0; e < 32; e++){
        int flat = e*256 + tid;
        int r = flat >> 6, c = flat & 63;
        int gm = m0 + (r >> 5);
        float y = Gb[(size_t)sidx[r]*64 + c] - g_C[gm*64 + c];
        xs[r*P1 + kperm(c)] = f2tf32(fmaxf(fmaf(g_aff[A0 + c], y, g_aff[C0A + c]), 0.f));
    }
    __syncthreads();

    float4 d[2][4];
#pragma unroll
    for (int mt = 0; mt < 2; mt++)
#pragma unroll
        for (int nt = 0; nt < 4; nt++) d[mt][nt] = make_float4(0.f,0.f,0.f,0.f);

    int xbase = (wr*32 + g)*P1;
    int wbase = (wc*32 + g)*P1;
#pragma unroll
    for (int kt = 0; kt < 8; kt++){
        int ko = kt*8 + 2*tig;
        uint32_t a[2][4];
#pragma unroll
        for (int mt = 0; mt < 2; mt++){
            int ro = xbase + mt*16*P1;
            uint2 a02 = *(const uint2*)&xs[ro + ko];
            uint2 a13 = *(const uint2*)&xs[ro + 8*P1 + ko];
            a[mt][0] = a02.x; a[mt][2] = a02.y;
            a[mt][1] = a13.x; a[mt][3] = a13.y;
        }
        uint32_t bf[4][2];
#pragma unroll
        for (int nt = 0; nt < 4; nt++){
            uint2 bv = *(const uint2*)&ws[wbase + nt*8*P1 + ko];
            bf[nt][0] = bv.x; bf[nt][1] = bv.y;
        }
#pragma unroll
        for (int nt = 0; nt < 4; nt++)
#pragma unroll
            for (int mt = 0; mt < 2; mt++)
                mma_tf32(d[mt][nt], a[mt], bf[nt]);
    }

    // epilogue: bias, store Y1, stats
#pragma unroll
    for (int nt = 0; nt < 4; nt++){
        int c0 = wc*32 + nt*8 + 2*tig;
        float bb0 = b1[c0], bb1 = b1[c0+1];
        float s0 = 0.f, s1v = 0.f, q0 = 0.f, q1v = 0.f;
#pragma unroll
        for (int mt = 0; mt < 2; mt++){
            size_t R = (size_t)m0*32 + wr*32 + mt*16 + g;
            float y00 = d[mt][nt].x + bb0, y01 = d[mt][nt].y + bb1;
            float y10 = d[mt][nt].z + bb0, y11 = d[mt][nt].w + bb1;
            *(float2*)&g_Y1[R*64 + c0]     = make_float2(y00, y01);
            *(float2*)&g_Y1[(R+8)*64 + c0] = make_float2(y10, y11);
            s0 += y00 + y10; s1v += y01 + y11;
            q0 += y00*y00 + y10*y10; q1v += y01*y01 + y11*y11;
        }
#pragma unroll
        for (int off = 16; off >= 4; off >>= 1){
            s0  += __shfl_down_sync(0xffffffffu, s0,  off);
            s1v += __shfl_down_sync(0xffffffffu, s1v, off);
            q0  += __shfl_down_sync(0xffffffffu, q0,  off);
            q1v += __shfl_down_sync(0xffffffffu, q1v, off);
        }
        if (g == 0){
            atomicAdd(&ssum[c0], s0);   atomicAdd(&ssum[c0+1], s1v);
            atomicAdd(&ssq[c0],  q0);   atomicAdd(&ssq[c0+1],  q1v);
        }
    }
    __syncthreads();
    if (tid < 64){
        int slot = blockIdx.x & 31;
        atomicAdd(&g_stats[SUM1 + tid*32 + slot], ssum[tid]);
        atomicAdd(&g_stats[SQ1  + tid*32 + slot], ssq[tid]);
    }
}

// ---------------- layer2: tf32 MMA, 256 thr, 64 rows x 128 cols, fused pool ----------------
#define P2 68
__global__ void __launch_bounds__(256) l2_kernel(const float* __restrict__ w2, const float* __restrict__ b2){
    extern __shared__ float smf[];
    uint32_t* xs  = (uint32_t*)smf;        // [64][P2]  (r, kperm)
    uint32_t* ws  = xs + 64*P2;            // [128][P2] (n, kperm)
    float* ssum = (float*)(ws + 128*P2);   // 128
    float* ssq  = ssum + 128;              // 128

    int tid = threadIdx.x;
    int w = tid >> 5, lane = tid & 31;
    int g = lane >> 2, tig = lane & 3;
    int wr = w >> 2, wc = w & 3;           // row-tile 0..1 (one center each), col-tile 0..3
    int m0 = blockIdx.x * 2;

    if (tid < 128){ ssum[tid] = 0.f; ssq[tid] = 0.f; }
    for (int i = tid; i < 128*64; i += 256){
        int c = i >> 6, k = i & 63;
        ws[c*P2 + kperm(k)] = f2tf32(w2[i]);
    }
    for (int i = tid; i < 64*64; i += 256){
        int r = i >> 6, k = i & 63;
        float y = g_Y1[((size_t)m0*32 + r)*64 + k];
        xs[r*P2 + kperm(k)] = f2tf32(fmaxf(fmaf(g_aff[A1 + k], y, g_aff[C1A + k]), 0.f));
    }
    __syncthreads();

    float4 d[2][4];
#pragma unroll
    for (int mt = 0; mt < 2; mt++)
#pragma unroll
        for (int nt = 0; nt < 4; nt++) d[mt][nt] = make_float4(0.f,0.f,0.f,0.f);

    int xbase = (wr*32 + g)*P2;
    int wbase = (wc*32 + g)*P2;
#pragma unroll
    for (int kt = 0; kt < 8; kt++){
        int ko = kt*8 + 2*tig;
        uint32_t a[2][4];
#pragma unroll
        for (int mt = 0; mt < 2; mt++){
            int ro = xbase + mt*16*P2;
            uint2 a02 = *(const uint2*)&xs[ro + ko];
            uint2 a13 = *(const uint2*)&xs[ro + 8*P2 + ko];
            a[mt][0] = a02.x; a[mt][2] = a02.y;
            a[mt][1] = a13.x; a[mt][3] = a13.y;
        }
        uint32_t bf[4][2];
#pragma unroll
        for (int nt = 0; nt < 4; nt++){
            uint2 bv = *(const uint2*)&ws[wbase + nt*8*P2 + ko];
            bf[nt][0] = bv.x; bf[nt][1] = bv.y;
        }
#pragma unroll
        for (int nt = 0; nt < 4; nt++)
#pragma unroll
            for (int mt = 0; mt < 2; mt++)
                mma_tf32(d[mt][nt], a[mt], bf[nt]);
    }

    // epilogue: bias, pool over center rows (within warp), stats
    int cent = m0 + wr;
#pragma unroll
    for (int nt = 0; nt < 4; nt++){
        int c0 = wc*32 + nt*8 + 2*tig;
        float bb0 = b2[c0], bb1 = b2[c0+1];
        float y00a = d[0][nt].x + bb0, y01a = d[0][nt].y + bb1;
        float y10a = d[0][nt].z + bb0, y11a = d[0][nt].w + bb1;
        float y00b = d[1][nt].x + bb0, y01b = d[1][nt].y + bb1;
        float y10b = d[1][nt].z + bb0, y11b = d[1][nt].w + bb1;
        float mx0 = fmaxf(fmaxf(y00a, y10a), fmaxf(y00b, y10b));
        float mx1 = fmaxf(fmaxf(y01a, y11a), fmaxf(y01b, y11b));
        float mn0 = fminf(fminf(y00a, y10a), fminf(y00b, y10b));
        float mn1 = fminf(fminf(y01a, y11a), fminf(y01b, y11b));
        float s0 = y00a + y10a + y00b + y10b;
        float s1v = y01a + y11a + y01b + y11b;
        float q0 = y00a*y00a + y10a*y10a + y00b*y00b + y10b*y10b;
        float q1v = y01a*y01a + y11a*y11a + y01b*y01b + y11b*y11b;
#pragma unroll
        for (int off = 16; off >= 4; off >>= 1){
            mx0 = fmaxf(mx0, __shfl_down_sync(0xffffffffu, mx0, off));
            mx1 = fmaxf(mx1, __shfl_down_sync(0xffffffffu, mx1, off));
            mn0 = fminf(mn0, __shfl_down_sync(0xffffffffu, mn0, off));
            mn1 = fminf(mn1, __shfl_down_sync(0xffffffffu, mn1, off));
            s0  += __shfl_down_sync(0xffffffffu, s0,  off);
            s1v += __shfl_down_sync(0xffffffffu, s1v, off);
            q0  += __shfl_down_sync(0xffffffffu, q0,  off);
            q1v += __shfl_down_sync(0xffffffffu, q1v, off);
        }
        if (g == 0){
            g_mx[(size_t)cent*128 + c0]   = mx0;
            g_mx[(size_t)cent*128 + c0+1] = mx1;
            g_mn[(size_t)cent*128 + c0]   = mn0;
            g_mn[(size_t)cent*128 + c0+1] = mn1;
            atomicAdd(&ssum[c0], s0);   atomicAdd(&ssum[c0+1], s1v);
            atomicAdd(&ssq[c0],  q0);   atomicAdd(&ssq[c0+1],  q1v);
        }
    }
    __syncthreads();
    if (tid < 128){
        int slot = blockIdx.x & 31;
        atomicAdd(&g_stats[SUM2 + tid*32 + slot], ssum[tid]);
        atomicAdd(&g_stats[SQ2  + tid*32 + slot], ssq[tid]);
    }
}

// ---------------- final: BN2+ReLU on pooled extremum ----------------
__global__ void out_kernel(float* __restrict__ out){
    int i = blockIdx.x*256 + threadIdx.x;   // NCTR_TOT*128
    int c = i & 127;
    float a = g_aff[A2 + c];
    float v = (a >= 0.f) ? g_mx[i] : g_mn[i];
    out[OUT_XYZ_ELEMS + i] = fmaxf(fmaf(a, v, g_aff[C2A + c]), 0.f);
}

// ---------------- host launcher ----------------
extern "C" void kernel_launch(void* const* d_in, const int* in_sizes, int n_in,
                              void* d_out, int out_size){
    const float* xyz   = (const float*)d_in[0];
    const float* feat  = (const float*)d_in[1];
    const float* w0 = (const float*)d_in[2];
    const float* b0 = (const float*)d_in[3];
    const float* g0 = (const float*)d_in[4];
    const float* be0 = (const float*)d_in[5];
    const float* w1 = (const float*)d_in[6];
    const float* b1 = (const float*)d_in[7];
    const float* g1 = (const float*)d_in[8];
    const float* be1 = (const float*)d_in[9];
    const float* w2 = (const float*)d_in[10];
    const float* b2 = (const float*)d_in[11];
    const float* g2 = (const float*)d_in[12];
    const float* be2 = (const float*)d_in[13];
    float* out = (float*)d_out;

    static const int MEGA_SMEM = (12288 + 64) * 4;                      // ~49.4 KB
    static const int L1_SMEM  = (128*P1 + 64*P1)*4 + 128*4 + 128*4;     // ~53.2 KB
    static const int L2_SMEM  = (64*P2 + 128*P2)*4 + 256*4;             // ~53.2 KB
    cudaFuncSetAttribute(mega_kernel, cudaFuncAttributeMaxDynamicSharedMemorySize, MEGA_SMEM);
    cudaFuncSetAttribute(l1_kernel,  cudaFuncAttributeMaxDynamicSharedMemorySize, L1_SMEM);
    cudaFuncSetAttribute(l2_kernel,  cudaFuncAttributeMaxDynamicSharedMemorySize, L2_SMEM);

    mega_kernel<<<FPS_NB + G_NB + BQ_NB, 256, MEGA_SMEM>>>(xyz, feat, w0, b0, out);
    fin_kernel<<<1, 128>>>(g0, be0, SUM0, SQ0, A0, C0A, 64);
    l1_kernel<<<NCTR_TOT/4, 256, L1_SMEM>>>(w1, b1);
    fin_kernel<<<1, 128>>>(g1, be1, SUM1, SQ1, A1, C1A, 64);
    l2_kernel<<<NCTR_TOT/2, 256, L2_SMEM>>>(w2, b2);
    fin_kernel<<<1, 128>>>(g2, be2, SUM2, SQ2, A2, C2A, 128);
    out_kernel<<<NCTR_TOT*128/256, 256>>>(out);
}